// round 1
// baseline (speedup 1.0000x reference)
#include <cuda_runtime.h>
#include <math.h>

#define EDIM 1024
#define HNUM 16
#define DDIM 64
#define MAXL 512
#define BATCH 4
#define SEQ 1024
#define ROWS (BATCH * SEQ)   // 4096
#define EPSV 1e-5f

// ---------------- scratch (device globals; no allocs allowed) ----------------
__device__ float g_xn [ROWS * EDIM];        // ln1(x)
__device__ float g_qkv[ROWS * 3 * EDIM];    // qkv projection
__device__ float g_att[ROWS * EDIM];        // attention output (b,n,e)
__device__ float g_x1 [ROWS * EDIM];        // x + attn out-proj (residual 1)
__device__ float g_xm [ROWS * EDIM];        // ln2(x1)
__device__ float g_h  [ROWS * 4 * EDIM];    // relu(ffn1)

// ---------------- LayerNorm: one block per row, 256 threads ----------------
__global__ void ln_kernel(const float* __restrict__ x,
                          const float* __restrict__ g,
                          const float* __restrict__ b,
                          float* __restrict__ out) {
    int row = blockIdx.x;
    int tid = threadIdx.x;            // 256 threads, 4 floats each
    const float4* xr = (const float4*)(x + (size_t)row * EDIM);
    float4 v = xr[tid];
    float s  = v.x + v.y + v.z + v.w;
    float ss = v.x * v.x + v.y * v.y + v.z * v.z + v.w * v.w;
#pragma unroll
    for (int o = 16; o > 0; o >>= 1) {
        s  += __shfl_xor_sync(0xffffffffu, s,  o);
        ss += __shfl_xor_sync(0xffffffffu, ss, o);
    }
    __shared__ float rs[8], rss[8];
    __shared__ float s_mu, s_rstd;
    if ((tid & 31) == 0) { rs[tid >> 5] = s; rss[tid >> 5] = ss; }
    __syncthreads();
    if (tid == 0) {
        float S = 0.f, SS = 0.f;
#pragma unroll
        for (int i = 0; i < 8; i++) { S += rs[i]; SS += rss[i]; }
        float mu = S * (1.0f / EDIM);
        float var = SS * (1.0f / EDIM) - mu * mu;
        s_mu = mu;
        s_rstd = rsqrtf(var + EPSV);
    }
    __syncthreads();
    float mu = s_mu, rstd = s_rstd;
    float4 gg = ((const float4*)g)[tid];
    float4 bb = ((const float4*)b)[tid];
    float4 o4;
    o4.x = (v.x - mu) * rstd * gg.x + bb.x;
    o4.y = (v.y - mu) * rstd * gg.y + bb.y;
    o4.z = (v.z - mu) * rstd * gg.z + bb.z;
    o4.w = (v.w - mu) * rstd * gg.w + bb.w;
    ((float4*)(out + (size_t)row * EDIM))[tid] = o4;
}

// ---------------- NT GEMM: C[M,Nc] = A[M,K] @ B[Nc,K]^T (+bias)(+relu)(+res) -
// Tiles: BM=128, BN=64, BK=16. 256 threads, 8x4 outputs/thread.
template <bool RELU, bool RES>
__global__ void __launch_bounds__(256, 2)
gemm_nt(const float* __restrict__ A, const float* __restrict__ Bm,
        const float* __restrict__ bias, const float* __restrict__ res,
        float* __restrict__ C, int M, int Nc, int K) {
    const int BM = 128, BN = 64, BK = 16;
    __shared__ float As[BK][BM];
    __shared__ float Bs[BK][BN];
    int tid = threadIdx.x;
    int ty = tid >> 4;       // 0..15 -> rows ty*8..ty*8+7
    int tx = tid & 15;       // 0..15 -> cols tx*4..tx*4+3
    int brow = blockIdx.y * BM;
    int bcol = blockIdx.x * BN;

    float acc[8][4];
#pragma unroll
    for (int i = 0; i < 8; i++)
#pragma unroll
        for (int j = 0; j < 4; j++) acc[i][j] = 0.f;

    for (int k0 = 0; k0 < K; k0 += BK) {
        // A tile: 128x16 = 512 float4, 2 per thread
#pragma unroll
        for (int i = 0; i < 2; i++) {
            int idx = tid + i * 256;      // float4 index
            int r  = idx >> 2;            // 4 float4 per row
            int c4 = idx & 3;
            float4 a4 = *((const float4*)(A + (size_t)(brow + r) * K + k0) + c4);
            As[c4 * 4 + 0][r] = a4.x;
            As[c4 * 4 + 1][r] = a4.y;
            As[c4 * 4 + 2][r] = a4.z;
            As[c4 * 4 + 3][r] = a4.w;
        }
        // B tile: 64x16 = 256 float4, 1 per thread
        {
            int r  = tid >> 2;
            int c4 = tid & 3;
            float4 b4 = *((const float4*)(Bm + (size_t)(bcol + r) * K + k0) + c4);
            Bs[c4 * 4 + 0][r] = b4.x;
            Bs[c4 * 4 + 1][r] = b4.y;
            Bs[c4 * 4 + 2][r] = b4.z;
            Bs[c4 * 4 + 3][r] = b4.w;
        }
        __syncthreads();
#pragma unroll
        for (int k = 0; k < BK; k++) {
            float4 a0 = *((float4*)&As[k][ty * 8]);
            float4 a1 = *((float4*)&As[k][ty * 8 + 4]);
            float4 b0 = *((float4*)&Bs[k][tx * 4]);
            float av[8] = {a0.x, a0.y, a0.z, a0.w, a1.x, a1.y, a1.z, a1.w};
            float bv[4] = {b0.x, b0.y, b0.z, b0.w};
#pragma unroll
            for (int i = 0; i < 8; i++)
#pragma unroll
                for (int j = 0; j < 4; j++) acc[i][j] += av[i] * bv[j];
        }
        __syncthreads();
    }

    int c = bcol + tx * 4;
    float4 bi = *((const float4*)&bias[c]);
#pragma unroll
    for (int i = 0; i < 8; i++) {
        int r = brow + ty * 8 + i;
        float4 v;
        v.x = acc[i][0] + bi.x;
        v.y = acc[i][1] + bi.y;
        v.z = acc[i][2] + bi.z;
        v.w = acc[i][3] + bi.w;
        if (RELU) {
            v.x = fmaxf(v.x, 0.f); v.y = fmaxf(v.y, 0.f);
            v.z = fmaxf(v.z, 0.f); v.w = fmaxf(v.w, 0.f);
        }
        if (RES) {
            float4 r4 = *((const float4*)&res[(size_t)r * Nc + c]);
            v.x += r4.x; v.y += r4.y; v.z += r4.z; v.w += r4.w;
        }
        *((float4*)&C[(size_t)r * Nc + c]) = v;
    }
}

// ---------------- Windowed attention: block = (query row, batch*head) -------
// bias(i,j) = rel_pos[h, i-j] if 0 <= i-j < 512 else -inf  => window [i-511, i]
__global__ void attn_kernel(const float* __restrict__ qkv,
                            const float* __restrict__ relp,
                            float* __restrict__ out) {
    int qi = blockIdx.x;
    int bh = blockIdx.y;
    int b = bh >> 4, h = bh & 15;
    int tid = threadIdx.x;            // 128 threads

    __shared__ float sq[DDIM];
    __shared__ float sc[MAXL];
    __shared__ float red[4], red2[4];
    __shared__ float pacc[DDIM];

    int jlo = qi - (MAXL - 1);
    if (jlo < 0) jlo = 0;
    int W = qi - jlo + 1;             // 1..512 valid keys

    const float* qrow = qkv + ((size_t)(b * SEQ + qi) * 3 * EDIM) + h * DDIM;
    if (tid < DDIM) sq[tid] = qrow[tid] * 0.125f;   // 1/sqrt(64)
    __syncthreads();

    // scores + local max
    float lmax = -1e30f;
    for (int jj = tid; jj < W; jj += 128) {
        int j = jlo + jj;
        const float* krow = qkv + ((size_t)(b * SEQ + j) * 3 * EDIM) + EDIM + h * DDIM;
        float dot = 0.f;
#pragma unroll
        for (int d4 = 0; d4 < 16; d4++) {
            float4 kv = ((const float4*)krow)[d4];
            float4 qv = ((const float4*)sq)[d4];
            dot += kv.x * qv.x + kv.y * qv.y + kv.z * qv.z + kv.w * qv.w;
        }
        dot += relp[h * MAXL + (qi - j)];
        sc[jj] = dot;
        lmax = fmaxf(lmax, dot);
    }
#pragma unroll
    for (int o = 16; o > 0; o >>= 1) lmax = fmaxf(lmax, __shfl_xor_sync(0xffffffffu, lmax, o));
    if ((tid & 31) == 0) red[tid >> 5] = lmax;
    __syncthreads();
    float mx = fmaxf(fmaxf(red[0], red[1]), fmaxf(red[2], red[3]));

    // exp + sum
    float lsum = 0.f;
    for (int jj = tid; jj < W; jj += 128) {
        float p = __expf(sc[jj] - mx);
        sc[jj] = p;
        lsum += p;
    }
#pragma unroll
    for (int o = 16; o > 0; o >>= 1) lsum += __shfl_xor_sync(0xffffffffu, lsum, o);
    if ((tid & 31) == 0) red2[tid >> 5] = lsum;
    __syncthreads();
    float inv = 1.0f / (red2[0] + red2[1] + red2[2] + red2[3]);

    // output: 64 dims x 2 key-partitions
    int d = tid & 63;
    int part = tid >> 6;
    float acc = 0.f;
    for (int jj = part; jj < W; jj += 2) {
        const float* vrow = qkv + ((size_t)(b * SEQ + jlo + jj) * 3 * EDIM) + 2 * EDIM + h * DDIM;
        acc += sc[jj] * vrow[d];
    }
    if (part == 1) pacc[d] = acc;
    __syncthreads();
    if (part == 0)
        out[((size_t)(b * SEQ + qi)) * EDIM + h * DDIM + d] = (acc + pacc[d]) * inv;
}

// ---------------- launch ----------------
extern "C" void kernel_launch(void* const* d_in, const int* in_sizes, int n_in,
                              void* d_out, int out_size) {
    (void)in_sizes; (void)n_in; (void)out_size;
    const float* x    = (const float*)d_in[0];
    const float* relp = (const float*)d_in[1];
    const float* ipw  = (const float*)d_in[2];
    const float* ipb  = (const float*)d_in[3];
    const float* ow   = (const float*)d_in[4];
    const float* ob   = (const float*)d_in[5];
    const float* w1   = (const float*)d_in[6];
    const float* b1   = (const float*)d_in[7];
    const float* w2   = (const float*)d_in[8];
    const float* b2   = (const float*)d_in[9];
    const float* g1   = (const float*)d_in[10];
    const float* be1  = (const float*)d_in[11];
    const float* g2   = (const float*)d_in[12];
    const float* be2  = (const float*)d_in[13];
    float* out = (float*)d_out;

    float *p_xn, *p_qkv, *p_att, *p_x1, *p_xm, *p_h;
    cudaGetSymbolAddress((void**)&p_xn,  g_xn);
    cudaGetSymbolAddress((void**)&p_qkv, g_qkv);
    cudaGetSymbolAddress((void**)&p_att, g_att);
    cudaGetSymbolAddress((void**)&p_x1,  g_x1);
    cudaGetSymbolAddress((void**)&p_xm,  g_xm);
    cudaGetSymbolAddress((void**)&p_h,   g_h);

    // 1. ln1
    ln_kernel<<<ROWS, 256>>>(x, g1, be1, p_xn);
    // 2. qkv = xn @ in_proj_w^T + in_proj_b   [4096,3072] K=1024
    gemm_nt<false, false><<<dim3(3072 / 64, ROWS / 128), 256>>>(
        p_xn, ipw, ipb, nullptr, p_qkv, ROWS, 3 * EDIM, EDIM);
    // 3. windowed attention
    attn_kernel<<<dim3(SEQ, BATCH * HNUM), 128>>>(p_qkv, relp, p_att);
    // 4. x1 = x + att @ out_w^T + out_b       [4096,1024] K=1024
    gemm_nt<false, true><<<dim3(1024 / 64, ROWS / 128), 256>>>(
        p_att, ow, ob, x, p_x1, ROWS, EDIM, EDIM);
    // 5. ln2
    ln_kernel<<<ROWS, 256>>>(p_x1, g2, be2, p_xm);
    // 6. h = relu(xm @ w1^T + b1)             [4096,4096] K=1024
    gemm_nt<true, false><<<dim3(4096 / 64, ROWS / 128), 256>>>(
        p_xm, w1, b1, nullptr, p_h, ROWS, 4 * EDIM, EDIM);
    // 7. out = x1 + h @ w2^T + b2             [4096,1024] K=4096
    gemm_nt<false, true><<<dim3(1024 / 64, ROWS / 128), 256>>>(
        p_h, w2, b2, p_x1, out, ROWS, EDIM, 4 * EDIM);
}

// round 4
// speedup vs baseline: 2.4675x; 2.4675x over previous
#include <cuda_runtime.h>
#include <cuda_bf16.h>
#include <math.h>
#include <stdint.h>

#define EDIM 1024
#define HNUM 16
#define DDIM 64
#define MAXL 512
#define BATCH 4
#define SEQ 1024
#define ROWS (BATCH * SEQ)   // 4096
#define EPSV 1e-5f

// ---------------- scratch (device globals; no allocs allowed) ----------------
__device__ float g_qkv[ROWS * 3 * EDIM];
__device__ float g_x1 [ROWS * EDIM];
__device__ __align__(16) __nv_bfloat16 g_xnh[ROWS * EDIM],  g_xnl[ROWS * EDIM];
__device__ __align__(16) __nv_bfloat16 g_atth[ROWS * EDIM], g_attl[ROWS * EDIM];
__device__ __align__(16) __nv_bfloat16 g_xmh[ROWS * EDIM],  g_xml[ROWS * EDIM];
__device__ __align__(16) __nv_bfloat16 g_hh[ROWS * 4 * EDIM], g_hl[ROWS * 4 * EDIM];
__device__ __align__(16) __nv_bfloat16 g_ipwh[3 * EDIM * EDIM], g_ipwl[3 * EDIM * EDIM];
__device__ __align__(16) __nv_bfloat16 g_owh [EDIM * EDIM],     g_owl [EDIM * EDIM];
__device__ __align__(16) __nv_bfloat16 g_w1h [4 * EDIM * EDIM], g_w1l [4 * EDIM * EDIM];
__device__ __align__(16) __nv_bfloat16 g_w2h [4 * EDIM * EDIM], g_w2l [4 * EDIM * EDIM];

// ======================= helpers =======================
__device__ __forceinline__ uint32_t smem_u32(const void* p) {
    uint32_t a;
    asm("{ .reg .u64 t; cvta.to.shared.u64 t, %1; cvt.u32.u64 %0, t; }" : "=r"(a) : "l"(p));
    return a;
}
__device__ __forceinline__ void cpa16(uint32_t dst, const void* src) {
    asm volatile("cp.async.cg.shared.global [%0], [%1], 16;" :: "r"(dst), "l"(src));
}
__device__ __forceinline__ void ldm4(uint32_t* r, uint32_t addr) {
    asm volatile("ldmatrix.sync.aligned.m8n8.x4.shared.b16 {%0,%1,%2,%3}, [%4];"
                 : "=r"(r[0]), "=r"(r[1]), "=r"(r[2]), "=r"(r[3]) : "r"(addr));
}
__device__ __forceinline__ void mma16816(float* c, const uint32_t* a, const uint32_t* b) {
    asm volatile(
        "mma.sync.aligned.m16n8k16.row.col.f32.bf16.bf16.f32 "
        "{%0,%1,%2,%3}, {%4,%5,%6,%7}, {%8,%9}, {%0,%1,%2,%3};"
        : "+f"(c[0]), "+f"(c[1]), "+f"(c[2]), "+f"(c[3])
        : "r"(a[0]), "r"(a[1]), "r"(a[2]), "r"(a[3]), "r"(b[0]), "r"(b[1]));
}
__device__ __forceinline__ void split_pair(float a, float b,
                                           __nv_bfloat162& h, __nv_bfloat162& l) {
    __nv_bfloat16 ha = __float2bfloat16(a), hb = __float2bfloat16(b);
    h = __halves2bfloat162(ha, hb);
    l = __halves2bfloat162(__float2bfloat16(a - __bfloat162float(ha)),
                           __float2bfloat16(b - __bfloat162float(hb)));
}

// ======================= weight split =======================
__global__ void split_kernel(const float4* __restrict__ w,
                             __nv_bfloat162* __restrict__ hi,
                             __nv_bfloat162* __restrict__ lo, int n4) {
    int i = blockIdx.x * 256 + threadIdx.x;
    if (i >= n4) return;
    float4 f = w[i];
    __nv_bfloat162 h0, l0, h1, l1;
    split_pair(f.x, f.y, h0, l0);
    split_pair(f.z, f.w, h1, l1);
    hi[2 * i] = h0; hi[2 * i + 1] = h1;
    lo[2 * i] = l0; lo[2 * i + 1] = l1;
}

// ======================= LayerNorm (fp32 in -> bf16 hi/lo out) ===============
__global__ void ln_kernel(const float* __restrict__ x,
                          const float* __restrict__ g,
                          const float* __restrict__ b,
                          __nv_bfloat16* __restrict__ oh,
                          __nv_bfloat16* __restrict__ ol) {
    int row = blockIdx.x;
    int tid = threadIdx.x;
    const float4* xr = (const float4*)(x + (size_t)row * EDIM);
    float4 v = xr[tid];
    float s  = v.x + v.y + v.z + v.w;
    float ss = v.x * v.x + v.y * v.y + v.z * v.z + v.w * v.w;
#pragma unroll
    for (int o = 16; o > 0; o >>= 1) {
        s  += __shfl_xor_sync(0xffffffffu, s,  o);
        ss += __shfl_xor_sync(0xffffffffu, ss, o);
    }
    __shared__ float rs[8], rss[8];
    __shared__ float s_mu, s_rstd;
    if ((tid & 31) == 0) { rs[tid >> 5] = s; rss[tid >> 5] = ss; }
    __syncthreads();
    if (tid == 0) {
        float S = 0.f, SS = 0.f;
#pragma unroll
        for (int i = 0; i < 8; i++) { S += rs[i]; SS += rss[i]; }
        float mu = S * (1.0f / EDIM);
        float var = SS * (1.0f / EDIM) - mu * mu;
        s_mu = mu; s_rstd = rsqrtf(var + EPSV);
    }
    __syncthreads();
    float mu = s_mu, rstd = s_rstd;
    float4 gg = ((const float4*)g)[tid];
    float4 bb = ((const float4*)b)[tid];
    float o0 = (v.x - mu) * rstd * gg.x + bb.x;
    float o1 = (v.y - mu) * rstd * gg.y + bb.y;
    float o2 = (v.z - mu) * rstd * gg.z + bb.z;
    float o3 = (v.w - mu) * rstd * gg.w + bb.w;
    __nv_bfloat162 h0, l0, h1, l1;
    split_pair(o0, o1, h0, l0);
    split_pair(o2, o3, h1, l1);
    __nv_bfloat162* ph = (__nv_bfloat162*)(oh + (size_t)row * EDIM);
    __nv_bfloat162* pl = (__nv_bfloat162*)(ol + (size_t)row * EDIM);
    ph[2 * tid] = h0; ph[2 * tid + 1] = h1;
    pl[2 * tid] = l0; pl[2 * tid + 1] = l1;
}

// ======================= mma.sync split-bf16 GEMM =======================
// C[4096,Nc] = A[4096,K] @ B[Nc,K]^T via (Ah+Al)(Bh+Bl) ~ AhBh + AhBl + AlBh.
// BM=128 BN=128 BK=32, 256 thr, 8 warps (2M x 4N), warp tile 64x32.
#define SROWB 80u             // 32 bf16 padded to 80B rows (conflict-free ldmatrix)
#define TILEB 10240u          // 128 rows * 80B
#define STAGEB (4u * TILEB)   // Ah, Al, Bh, Bl
#define GSMEM (2u * STAGEB)   // double buffered = 81920B

template <bool RELU, bool RES, bool OUTF32, bool OUTSPLIT>
__global__ void __launch_bounds__(256)
gemm_mma(const __nv_bfloat16* __restrict__ Ah, const __nv_bfloat16* __restrict__ Al,
         const __nv_bfloat16* __restrict__ Bh, const __nv_bfloat16* __restrict__ Bl,
         const float* __restrict__ bias, const float* __restrict__ res,
         float* __restrict__ C, __nv_bfloat16* __restrict__ Chi,
         __nv_bfloat16* __restrict__ Clo, int Nc, int K) {
    extern __shared__ char sm[];
    uint32_t sb = smem_u32(sm);
    int tid = threadIdx.x;
    int wid = tid >> 5, lane = tid & 31;
    int wm = wid & 1, wn = wid >> 1;
    int brow = blockIdx.y * 128, bcol = blockIdx.x * 128;

    float acc[4][4][4];
#pragma unroll
    for (int i = 0; i < 4; i++)
#pragma unroll
        for (int j = 0; j < 4; j++)
#pragma unroll
            for (int k = 0; k < 4; k++) acc[i][j][k] = 0.f;

    int nchunk = K >> 5;
    // --- stage loader ---
    auto load_stage = [&](int st, int k0) {
        uint32_t base = sb + (uint32_t)st * STAGEB;
#pragma unroll
        for (int i = 0; i < 2; i++) {
            int idx = tid + i * 256;          // 0..511
            int r = idx >> 2, c = idx & 3;    // row, 16B chunk
            size_t goA = (size_t)(brow + r) * K + k0 + c * 8;
            size_t goB = (size_t)(bcol + r) * K + k0 + c * 8;
            uint32_t d = base + (uint32_t)(r * SROWB + c * 16);
            cpa16(d,             Ah + goA);
            cpa16(d + TILEB,     Al + goA);
            cpa16(d + 2 * TILEB, Bh + goB);
            cpa16(d + 3 * TILEB, Bl + goB);
        }
    };

    load_stage(0, 0);
    asm volatile("cp.async.commit_group;" ::: "memory");

    int l15 = lane & 15;
    int ahalf = (lane & 16) ? 16 : 0;                 // A col +16B half
    int brr = (lane & 7) + ((lane & 16) ? 8 : 0);     // B row within 16
    int bhalf = (lane & 8) ? 16 : 0;                  // B col +16B half

    for (int ch = 0; ch < nchunk; ch++) {
        if (ch + 1 < nchunk) load_stage((ch + 1) & 1, (ch + 1) * 32);
        asm volatile("cp.async.commit_group;" ::: "memory");
        asm volatile("cp.async.wait_group 1;" ::: "memory");
        __syncthreads();

        uint32_t base = sb + (uint32_t)(ch & 1) * STAGEB;
#pragma unroll
        for (int ks = 0; ks < 2; ks++) {
            uint32_t bh[2][4], bl[2][4];
#pragma unroll
            for (int p = 0; p < 2; p++) {
                uint32_t rb = base + 2 * TILEB +
                    (uint32_t)((wn * 32 + p * 16 + brr) * SROWB + ks * 32 + bhalf);
                ldm4(bh[p], rb);
                ldm4(bl[p], rb + TILEB);
            }
#pragma unroll
            for (int mf = 0; mf < 4; mf++) {
                uint32_t ah[4], al[4];
                uint32_t ra = base +
                    (uint32_t)((wm * 64 + mf * 16 + l15) * SROWB + ks * 32 + ahalf);
                ldm4(ah, ra);
                ldm4(al, ra + TILEB);
#pragma unroll
                for (int nf = 0; nf < 4; nf++) {
                    const uint32_t* ph = &bh[nf >> 1][(nf & 1) * 2];
                    const uint32_t* pl = &bl[nf >> 1][(nf & 1) * 2];
                    mma16816(acc[mf][nf], ah, ph);
                    mma16816(acc[mf][nf], ah, pl);
                    mma16816(acc[mf][nf], al, ph);
                }
            }
        }
        __syncthreads();
    }

    // --- epilogue ---
    int gid = lane >> 2, tig = lane & 3;
#pragma unroll
    for (int mf = 0; mf < 4; mf++) {
#pragma unroll
        for (int nf = 0; nf < 4; nf++) {
            int col = bcol + wn * 32 + nf * 8 + tig * 2;
            float b0 = bias[col], b1 = bias[col + 1];
#pragma unroll
            for (int hr = 0; hr < 2; hr++) {
                int row = brow + wm * 64 + mf * 16 + gid + hr * 8;
                float v0 = acc[mf][nf][hr * 2 + 0] + b0;
                float v1 = acc[mf][nf][hr * 2 + 1] + b1;
                if (RELU) { v0 = fmaxf(v0, 0.f); v1 = fmaxf(v1, 0.f); }
                if (RES) {
                    float2 r2 = *(const float2*)(res + (size_t)row * Nc + col);
                    v0 += r2.x; v1 += r2.y;
                }
                if (OUTF32) {
                    float2 o2; o2.x = v0; o2.y = v1;
                    *(float2*)(C + (size_t)row * Nc + col) = o2;
                }
                if (OUTSPLIT) {
                    __nv_bfloat162 h2, l2;
                    split_pair(v0, v1, h2, l2);
                    *(__nv_bfloat162*)(Chi + (size_t)row * Nc + col) = h2;
                    *(__nv_bfloat162*)(Clo + (size_t)row * Nc + col) = l2;
                }
            }
        }
    }
}

// ======================= tiled windowed attention =======================
// Block: 64 queries x one (b,h). Key tiles of 64, <=9 per q-tile (512 window).
#define APAD 68
__global__ void __launch_bounds__(256)
attn_kernel(const float* __restrict__ qkv, const float* __restrict__ relp,
            __nv_bfloat16* __restrict__ outh, __nv_bfloat16* __restrict__ outl) {
    extern __shared__ float smf[];
    float* sQ = smf;
    float* sK = sQ + 64 * APAD;
    float* sV = sK + 64 * APAD;
    float* sP = sV + 64 * APAD;
    int tid = threadIdx.x;
    int qt = blockIdx.x; int q0 = qt * 64;
    int bh = blockIdx.y; int b = bh >> 4, h = bh & 15;

#pragma unroll
    for (int i = 0; i < 4; i++) {
        int e4 = tid + i * 256;
        int r = e4 >> 4, d4 = e4 & 15;
        float4 f = *(const float4*)(qkv + (size_t)(b * SEQ + q0 + r) * 3 * EDIM +
                                    h * DDIM + d4 * 4);
        f.x *= 0.125f; f.y *= 0.125f; f.z *= 0.125f; f.w *= 0.125f;
        *(float4*)(sQ + r * APAD + d4 * 4) = f;
    }

    int q = tid >> 2, quad = tid & 3;
    int qi = q0 + q;
    float accd[16];
#pragma unroll
    for (int dd = 0; dd < 16; dd++) accd[dd] = 0.f;
    float m = -1e30f, l = 0.f;

    int kt0 = qt - 8; if (kt0 < 0) kt0 = 0;
    for (int kt = kt0; kt <= qt; kt++) {
        int k0 = kt * 64;
        __syncthreads();
#pragma unroll
        for (int i = 0; i < 4; i++) {
            int e4 = tid + i * 256;
            int r = e4 >> 4, d4 = e4 & 15;
            const float* src = qkv + (size_t)(b * SEQ + k0 + r) * 3 * EDIM + h * DDIM + d4 * 4;
            *(float4*)(sK + r * APAD + d4 * 4) = *(const float4*)(src + EDIM);
            *(float4*)(sV + r * APAD + d4 * 4) = *(const float4*)(src + 2 * EDIM);
        }
        __syncthreads();

        float s[16];
#pragma unroll
        for (int kk = 0; kk < 16; kk++) s[kk] = 0.f;
#pragma unroll 4
        for (int d4 = 0; d4 < 16; d4++) {
            float4 qv = *(float4*)(sQ + q * APAD + d4 * 4);
#pragma unroll
            for (int kk = 0; kk < 16; kk++) {
                float4 kv = *(float4*)(sK + (quad + kk * 4) * APAD + d4 * 4);
                s[kk] += qv.x * kv.x + qv.y * kv.y + qv.z * kv.z + qv.w * kv.w;
            }
        }
        float mt = -1e30f;
#pragma unroll
        for (int kk = 0; kk < 16; kk++) {
            int j = k0 + quad + kk * 4;
            int rel = qi - j;
            bool valid = (rel >= 0) && (rel < MAXL);
            s[kk] = valid ? s[kk] + relp[h * MAXL + (valid ? rel : 0)] : -1e30f;
            mt = fmaxf(mt, s[kk]);
        }
        mt = fmaxf(mt, __shfl_xor_sync(0xffffffffu, mt, 1));
        mt = fmaxf(mt, __shfl_xor_sync(0xffffffffu, mt, 2));
        float mn = fmaxf(m, mt);
        float alpha = __expf(m - mn);
        float ssum = 0.f;
#pragma unroll
        for (int kk = 0; kk < 16; kk++) {
            int j = k0 + quad + kk * 4;
            int rel = qi - j;
            bool valid = (rel >= 0) && (rel < MAXL);
            float pv = valid ? __expf(s[kk] - mn) : 0.f;
            sP[q * APAD + quad + kk * 4] = pv;
            ssum += pv;
        }
        ssum += __shfl_xor_sync(0xffffffffu, ssum, 1);
        ssum += __shfl_xor_sync(0xffffffffu, ssum, 2);
        l = l * alpha + ssum;
        m = mn;
#pragma unroll
        for (int dd = 0; dd < 16; dd++) accd[dd] *= alpha;
        __syncthreads();

        int d0 = quad * 16;
        for (int j4 = 0; j4 < 16; j4++) {
            float4 p4 = *(float4*)(sP + q * APAD + j4 * 4);
            float pj[4] = {p4.x, p4.y, p4.z, p4.w};
#pragma unroll
            for (int jj = 0; jj < 4; jj++) {
                int j = j4 * 4 + jj;
#pragma unroll
                for (int d4 = 0; d4 < 4; d4++) {
                    float4 vv = *(float4*)(sV + j * APAD + d0 + d4 * 4);
                    accd[d4 * 4 + 0] += pj[jj] * vv.x;
                    accd[d4 * 4 + 1] += pj[jj] * vv.y;
                    accd[d4 * 4 + 2] += pj[jj] * vv.z;
                    accd[d4 * 4 + 3] += pj[jj] * vv.w;
                }
            }
        }
    }
    float inv = 1.0f / l;
    size_t ob = (size_t)(b * SEQ + qi) * EDIM + h * DDIM + quad * 16;
#pragma unroll
    for (int dd = 0; dd < 16; dd += 2) {
        __nv_bfloat162 h2, l2;
        split_pair(accd[dd] * inv, accd[dd + 1] * inv, h2, l2);
        *(__nv_bfloat162*)(outh + ob + dd) = h2;
        *(__nv_bfloat162*)(outl + ob + dd) = l2;
    }
}

// ======================= launch =======================
extern "C" void kernel_launch(void* const* d_in, const int* in_sizes, int n_in,
                              void* d_out, int out_size) {
    (void)in_sizes; (void)n_in; (void)out_size;
    const float* x    = (const float*)d_in[0];
    const float* relp = (const float*)d_in[1];
    const float* ipw  = (const float*)d_in[2];
    const float* ipb  = (const float*)d_in[3];
    const float* ow   = (const float*)d_in[4];
    const float* ob   = (const float*)d_in[5];
    const float* w1   = (const float*)d_in[6];
    const float* b1   = (const float*)d_in[7];
    const float* w2   = (const float*)d_in[8];
    const float* b2   = (const float*)d_in[9];
    const float* g1   = (const float*)d_in[10];
    const float* be1  = (const float*)d_in[11];
    const float* g2   = (const float*)d_in[12];
    const float* be2  = (const float*)d_in[13];
    float* out = (float*)d_out;

    float *p_qkv, *p_x1;
    __nv_bfloat16 *p_xnh, *p_xnl, *p_atth, *p_attl, *p_xmh, *p_xml, *p_hh, *p_hl;
    __nv_bfloat16 *p_ipwh, *p_ipwl, *p_owh, *p_owl, *p_w1h, *p_w1l, *p_w2h, *p_w2l;
    cudaGetSymbolAddress((void**)&p_qkv, g_qkv);
    cudaGetSymbolAddress((void**)&p_x1,  g_x1);
    cudaGetSymbolAddress((void**)&p_xnh, g_xnh);   cudaGetSymbolAddress((void**)&p_xnl, g_xnl);
    cudaGetSymbolAddress((void**)&p_atth, g_atth); cudaGetSymbolAddress((void**)&p_attl, g_attl);
    cudaGetSymbolAddress((void**)&p_xmh, g_xmh);   cudaGetSymbolAddress((void**)&p_xml, g_xml);
    cudaGetSymbolAddress((void**)&p_hh,  g_hh);    cudaGetSymbolAddress((void**)&p_hl,  g_hl);
    cudaGetSymbolAddress((void**)&p_ipwh, g_ipwh); cudaGetSymbolAddress((void**)&p_ipwl, g_ipwl);
    cudaGetSymbolAddress((void**)&p_owh, g_owh);   cudaGetSymbolAddress((void**)&p_owl, g_owl);
    cudaGetSymbolAddress((void**)&p_w1h, g_w1h);   cudaGetSymbolAddress((void**)&p_w1l, g_w1l);
    cudaGetSymbolAddress((void**)&p_w2h, g_w2h);   cudaGetSymbolAddress((void**)&p_w2l, g_w2l);

    cudaFuncSetAttribute(gemm_mma<false, false, true, false>,
                         cudaFuncAttributeMaxDynamicSharedMemorySize, GSMEM);
    cudaFuncSetAttribute(gemm_mma<false, true, true, false>,
                         cudaFuncAttributeMaxDynamicSharedMemorySize, GSMEM);
    cudaFuncSetAttribute(gemm_mma<true, false, false, true>,
                         cudaFuncAttributeMaxDynamicSharedMemorySize, GSMEM);
    cudaFuncSetAttribute(attn_kernel,
                         cudaFuncAttributeMaxDynamicSharedMemorySize, 4 * 64 * APAD * 4);

    // weight splits
    split_kernel<<<3 * EDIM * EDIM / 1024, 256>>>((const float4*)ipw,
        (__nv_bfloat162*)p_ipwh, (__nv_bfloat162*)p_ipwl, 3 * EDIM * EDIM / 4);
    split_kernel<<<EDIM * EDIM / 1024, 256>>>((const float4*)ow,
        (__nv_bfloat162*)p_owh, (__nv_bfloat162*)p_owl, EDIM * EDIM / 4);
    split_kernel<<<4 * EDIM * EDIM / 1024, 256>>>((const float4*)w1,
        (__nv_bfloat162*)p_w1h, (__nv_bfloat162*)p_w1l, 4 * EDIM * EDIM / 4);
    split_kernel<<<4 * EDIM * EDIM / 1024, 256>>>((const float4*)w2,
        (__nv_bfloat162*)p_w2h, (__nv_bfloat162*)p_w2l, 4 * EDIM * EDIM / 4);

    // 1. ln1 -> xn hi/lo
    ln_kernel<<<ROWS, 256>>>(x, g1, be1, p_xnh, p_xnl);
    // 2. qkv = xn @ ipw^T + ipb (fp32 out)
    gemm_mma<false, false, true, false><<<dim3(3072 / 128, 32), 256, GSMEM>>>(
        p_xnh, p_xnl, p_ipwh, p_ipwl, ipb, nullptr, p_qkv, nullptr, nullptr,
        3 * EDIM, EDIM);
    // 3. attention -> att hi/lo
    attn_kernel<<<dim3(SEQ / 64, BATCH * HNUM), 256, 4 * 64 * APAD * 4>>>(
        p_qkv, relp, p_atth, p_attl);
    // 4. x1 = x + att @ ow^T + ob (fp32 out)
    gemm_mma<false, true, true, false><<<dim3(1024 / 128, 32), 256, GSMEM>>>(
        p_atth, p_attl, p_owh, p_owl, ob, x, p_x1, nullptr, nullptr, EDIM, EDIM);
    // 5. ln2 -> xm hi/lo
    ln_kernel<<<ROWS, 256>>>(p_x1, g2, be2, p_xmh, p_xml);
    // 6. h = relu(xm @ w1^T + b1) -> bf16 hi/lo only
    gemm_mma<true, false, false, true><<<dim3(4096 / 128, 32), 256, GSMEM>>>(
        p_xmh, p_xml, p_w1h, p_w1l, b1, nullptr, nullptr, p_hh, p_hl,
        4 * EDIM, EDIM);
    // 7. out = x1 + h @ w2^T + b2 (fp32 out)
    gemm_mma<false, true, true, false><<<dim3(1024 / 128, 32), 256, GSMEM>>>(
        p_hh, p_hl, p_w2h, p_w2l, b2, p_x1, out, nullptr, nullptr, EDIM, 4 * EDIM);
}

// round 9
// speedup vs baseline: 7.2970x; 2.9572x over previous
#include <cuda_runtime.h>
#include <cuda_fp16.h>
#include <math.h>
#include <stdint.h>

#define EDIM 1024
#define HNUM 16
#define DDIM 64
#define MAXL 512
#define BATCH 4
#define SEQ 1024
#define ROWS (BATCH * SEQ)   // 4096
#define EPSV 1e-5f

// ---------------- scratch ----------------
__device__ float g_x1[ROWS * EDIM];
__device__ __align__(16) __half g_xn  [ROWS * EDIM];
__device__ __align__(16) __half g_qkvh[ROWS * 3 * EDIM];
__device__ __align__(16) __half g_att [ROWS * EDIM];
__device__ __align__(16) __half g_xm  [ROWS * EDIM];
__device__ __align__(16) __half g_hb  [ROWS * 4 * EDIM];
__device__ __align__(16) __half g_ipwh[3 * EDIM * EDIM], g_ipwl[3 * EDIM * EDIM];
__device__ __align__(16) __half g_owh [EDIM * EDIM],     g_owl [EDIM * EDIM];
__device__ __align__(16) __half g_w1h [4 * EDIM * EDIM], g_w1l [4 * EDIM * EDIM];
__device__ __align__(16) __half g_w2h [4 * EDIM * EDIM], g_w2l [4 * EDIM * EDIM];

// ======================= helpers =======================
__device__ __forceinline__ uint32_t smem_u32(const void* p) {
    uint32_t a;
    asm("{ .reg .u64 t; cvta.to.shared.u64 t, %1; cvt.u32.u64 %0, t; }" : "=r"(a) : "l"(p));
    return a;
}
__device__ __forceinline__ void cpa16(uint32_t dst, const void* src) {
    asm volatile("cp.async.cg.shared.global [%0], [%1], 16;" :: "r"(dst), "l"(src));
}
__device__ __forceinline__ void ldm4(uint32_t* r, uint32_t addr) {
    asm volatile("ldmatrix.sync.aligned.m8n8.x4.shared.b16 {%0,%1,%2,%3}, [%4];"
                 : "=r"(r[0]), "=r"(r[1]), "=r"(r[2]), "=r"(r[3]) : "r"(addr));
}
__device__ __forceinline__ void ldm4t(uint32_t* r, uint32_t addr) {
    asm volatile("ldmatrix.sync.aligned.m8n8.x4.trans.shared.b16 {%0,%1,%2,%3}, [%4];"
                 : "=r"(r[0]), "=r"(r[1]), "=r"(r[2]), "=r"(r[3]) : "r"(addr));
}
__device__ __forceinline__ void mma16816(float* c, const uint32_t* a, const uint32_t* b) {
    asm volatile(
        "mma.sync.aligned.m16n8k16.row.col.f32.f16.f16.f32 "
        "{%0,%1,%2,%3}, {%4,%5,%6,%7}, {%8,%9}, {%0,%1,%2,%3};"
        : "+f"(c[0]), "+f"(c[1]), "+f"(c[2]), "+f"(c[3])
        : "r"(a[0]), "r"(a[1]), "r"(a[2]), "r"(a[3]), "r"(b[0]), "r"(b[1]));
}
__device__ __forceinline__ uint32_t packh2(float a, float b) {
    __half2 h = __floats2half2_rn(a, b);
    return *(uint32_t*)&h;
}
// XOR swizzle for 128B rows: 16B chunk c16 of row r
__device__ __forceinline__ uint32_t swz(int r, int c16) {
    return (uint32_t)(r * 128 + ((c16 ^ (r & 7)) << 4));
}

// ======================= weight split fp16 hi/lo =======================
__global__ void split_kernel(const float4* __restrict__ w,
                             __half2* __restrict__ hi,
                             __half2* __restrict__ lo, int n4) {
    int i = blockIdx.x * 256 + threadIdx.x;
    if (i >= n4) return;
    float4 f = w[i];
    float h0 = __half2float(__float2half_rn(f.x));
    float h1 = __half2float(__float2half_rn(f.y));
    float h2 = __half2float(__float2half_rn(f.z));
    float h3 = __half2float(__float2half_rn(f.w));
    hi[2 * i]     = __floats2half2_rn(h0, h1);
    hi[2 * i + 1] = __floats2half2_rn(h2, h3);
    lo[2 * i]     = __floats2half2_rn(f.x - h0, f.y - h1);
    lo[2 * i + 1] = __floats2half2_rn(f.z - h2, f.w - h3);
}

// ======================= LayerNorm (fp32 -> fp16) =======================
__global__ void ln_kernel(const float* __restrict__ x,
                          const float* __restrict__ g,
                          const float* __restrict__ b,
                          __half* __restrict__ o) {
    int row = blockIdx.x;
    int tid = threadIdx.x;
    const float4* xr = (const float4*)(x + (size_t)row * EDIM);
    float4 v = xr[tid];
    float s  = v.x + v.y + v.z + v.w;
    float ss = v.x * v.x + v.y * v.y + v.z * v.z + v.w * v.w;
#pragma unroll
    for (int of = 16; of > 0; of >>= 1) {
        s  += __shfl_xor_sync(0xffffffffu, s,  of);
        ss += __shfl_xor_sync(0xffffffffu, ss, of);
    }
    __shared__ float rs[8], rss[8];
    __shared__ float s_mu, s_rstd;
    if ((tid & 31) == 0) { rs[tid >> 5] = s; rss[tid >> 5] = ss; }
    __syncthreads();
    if (tid == 0) {
        float S = 0.f, SS = 0.f;
#pragma unroll
        for (int i = 0; i < 8; i++) { S += rs[i]; SS += rss[i]; }
        float mu = S * (1.0f / EDIM);
        float var = SS * (1.0f / EDIM) - mu * mu;
        s_mu = mu; s_rstd = rsqrtf(var + EPSV);
    }
    __syncthreads();
    float mu = s_mu, rstd = s_rstd;
    float4 gg = ((const float4*)g)[tid];
    float4 bb = ((const float4*)b)[tid];
    __half2* po = (__half2*)(o + (size_t)row * EDIM);
    po[2 * tid]     = __floats2half2_rn((v.x - mu) * rstd * gg.x + bb.x,
                                        (v.y - mu) * rstd * gg.y + bb.y);
    po[2 * tid + 1] = __floats2half2_rn((v.z - mu) * rstd * gg.z + bb.z,
                                        (v.w - mu) * rstd * gg.w + bb.w);
}

// ======================= fp16 2-term GEMM =======================
// C[4096,Nc] = A[4096,K] @ (Bh+Bl)[Nc,K]^T, A fp16, W hi/lo fp16.
// BM=128 BN=128 BK=64, 256 thr, 8 warps (2M x 4N), warp tile 64x32.
#define TIL 16384u                 // 128 rows * 128B
#define STG (3u * TIL)             // A, Bh, Bl
#define GSMEM (2u * STG)           // 98304

template <bool RELU, bool RES, bool OUTF32>
__global__ void __launch_bounds__(256)
gemm_mma(const __half* __restrict__ A,
         const __half* __restrict__ Bh, const __half* __restrict__ Bl,
         const float* __restrict__ bias, const float* __restrict__ res,
         float* __restrict__ C, __half* __restrict__ Ch, int Nc, int K) {
    extern __shared__ char sm[];
    uint32_t sb = smem_u32(sm);
    int tid = threadIdx.x;
    int wid = tid >> 5, lane = tid & 31;
    int wm = wid & 1, wn = wid >> 1;
    int brow = blockIdx.y * 128, bcol = blockIdx.x * 128;

    float acc[4][4][4];
#pragma unroll
    for (int i = 0; i < 4; i++)
#pragma unroll
        for (int j = 0; j < 4; j++)
#pragma unroll
            for (int k = 0; k < 4; k++) acc[i][j][k] = 0.f;

    int nchunk = K >> 6;
    auto load_stage = [&](int st, int k0) {
        uint32_t base = sb + (uint32_t)st * STG;
#pragma unroll
        for (int i = 0; i < 12; i++) {
            int idx = tid + i * 256;          // 0..3071
            int part = idx >> 10;             // 0=A 1=Bh 2=Bl
            int r = (idx & 1023) >> 3, c16 = idx & 7;
            uint32_t d = base + part * TIL + swz(r, c16);
            const __half* src = (part == 0) ? A + (size_t)(brow + r) * K + k0 + c16 * 8
                              : (part == 1) ? Bh + (size_t)(bcol + r) * K + k0 + c16 * 8
                                            : Bl + (size_t)(bcol + r) * K + k0 + c16 * 8;
            cpa16(d, src);
        }
    };

    load_stage(0, 0);
    asm volatile("cp.async.commit_group;" ::: "memory");

    int l15 = lane & 15;
    int ac16 = (lane & 16) ? 1 : 0;
    int brr = (lane & 7) + ((lane & 16) ? 8 : 0);
    int bc16 = (lane & 8) ? 1 : 0;

    for (int ch = 0; ch < nchunk; ch++) {
        if (ch + 1 < nchunk) load_stage((ch + 1) & 1, (ch + 1) * 64);
        asm volatile("cp.async.commit_group;" ::: "memory");
        asm volatile("cp.async.wait_group 1;" ::: "memory");
        __syncthreads();

        uint32_t base = sb + (uint32_t)(ch & 1) * STG;
#pragma unroll
        for (int kc = 0; kc < 4; kc++) {
            uint32_t bh[2][4], bl[2][4];
#pragma unroll
            for (int p = 0; p < 2; p++) {
                uint32_t ro = swz(wn * 32 + p * 16 + brr, kc * 2 + bc16);
                ldm4(bh[p], base + TIL + ro);
                ldm4(bl[p], base + 2 * TIL + ro);
            }
#pragma unroll
            for (int mf = 0; mf < 4; mf++) {
                uint32_t a[4];
                ldm4(a, base + swz(wm * 64 + mf * 16 + l15, kc * 2 + ac16));
#pragma unroll
                for (int nf = 0; nf < 4; nf++) {
                    mma16816(acc[mf][nf], a, &bh[nf >> 1][(nf & 1) * 2]);
                    mma16816(acc[mf][nf], a, &bl[nf >> 1][(nf & 1) * 2]);
                }
            }
        }
        __syncthreads();
    }

    int gid = lane >> 2, tig = lane & 3;
#pragma unroll
    for (int mf = 0; mf < 4; mf++) {
#pragma unroll
        for (int nf = 0; nf < 4; nf++) {
            int col = bcol + wn * 32 + nf * 8 + tig * 2;
            float b0 = bias[col], b1 = bias[col + 1];
#pragma unroll
            for (int hr = 0; hr < 2; hr++) {
                int row = brow + wm * 64 + mf * 16 + gid + hr * 8;
                float v0 = acc[mf][nf][hr * 2 + 0] + b0;
                float v1 = acc[mf][nf][hr * 2 + 1] + b1;
                if (RELU) { v0 = fmaxf(v0, 0.f); v1 = fmaxf(v1, 0.f); }
                if (RES) {
                    float2 r2 = *(const float2*)(res + (size_t)row * Nc + col);
                    v0 += r2.x; v1 += r2.y;
                }
                if (OUTF32) {
                    float2 o2; o2.x = v0; o2.y = v1;
                    *(float2*)(C + (size_t)row * Nc + col) = o2;
                } else {
                    *(__half2*)(Ch + (size_t)row * Nc + col) = __floats2half2_rn(v0, v1);
                }
            }
        }
    }
}

// ======================= flash attention (mma.sync fp16) =======================
// Block: 64 queries x (b,h); 4 warps, warp = 16 queries. Key tiles of 64.
#define AT_SQ   0u
#define AT_RP   8192u
#define AT_ST   10240u             // stages: [K 8192 | V 8192] x2
#define AT_SMEM (10240u + 2u * 16384u)

__global__ void __launch_bounds__(128)
attn_kernel(const __half* __restrict__ qkv, const float* __restrict__ relp,
            __half* __restrict__ outp) {
    extern __shared__ char sm[];
    uint32_t sb = smem_u32(sm);
    float* srelp = (float*)(sm + AT_RP);
    int tid = threadIdx.x;
    int w = tid >> 5, lane = tid & 31;
    int gid = lane >> 2, tig = lane & 3;
    int qt = blockIdx.x, q0 = qt * 64;
    int bh = blockIdx.y;
    int b = bh >> 4, h = bh & 15;

    // stage relp row (fp32) and Q tile (fp16, swizzled)
#pragma unroll
    for (int i = 0; i < 4; i++) srelp[tid + i * 128] = relp[h * MAXL + tid + i * 128];
#pragma unroll
    for (int i = 0; i < 4; i++) {
        int idx = tid + i * 128;              // 512 chunks
        int r = idx >> 3, c16 = idx & 7;
        uint4 q4 = *(const uint4*)(qkv + (size_t)(b * SEQ + q0 + r) * 3 * EDIM +
                                   h * DDIM + c16 * 8);
        *(uint4*)(sm + AT_SQ + swz(r, c16)) = q4;
    }
    __syncthreads();

    // Q frags: m16k64 per warp
    uint32_t qf[4][4];
    int l15 = lane & 15;
    int ac16 = (lane & 16) ? 1 : 0;
#pragma unroll
    for (int kc = 0; kc < 4; kc++)
        ldm4(qf[kc], sb + AT_SQ + swz(w * 16 + l15, kc * 2 + ac16));

    float o[8][4];
#pragma unroll
    for (int nf = 0; nf < 8; nf++)
#pragma unroll
        for (int e = 0; e < 4; e++) o[nf][e] = 0.f;
    float m0 = -1e30f, m1 = -1e30f, l0 = 0.f, l1 = 0.f;

    int kt0 = qt - 8; if (kt0 < 0) kt0 = 0;
    int nt = qt - kt0 + 1;

    auto load_kv = [&](int st, int kt) {
        uint32_t base = sb + AT_ST + (uint32_t)st * 16384u;
        int k0 = kt * 64;
#pragma unroll
        for (int i = 0; i < 8; i++) {
            int idx = tid + i * 128;          // 0..1023; 512 K then 512 V
            int part = idx >> 9;
            int r = (idx & 511) >> 3, c16 = idx & 7;
            const __half* src = qkv + (size_t)(b * SEQ + k0 + r) * 3 * EDIM +
                                (part ? 2 * EDIM : EDIM) + h * DDIM + c16 * 8;
            cpa16(base + part * 8192u + swz(r, c16), src);
        }
    };

    load_kv(0, kt0);
    asm volatile("cp.async.commit_group;" ::: "memory");

    int brr = (lane & 7) + ((lane & 16) ? 8 : 0);
    int bc16 = (lane & 8) ? 1 : 0;
    int vrr = (lane & 7) + ((lane & 8) ? 8 : 0);
    int vc16 = (lane & 16) ? 1 : 0;

    for (int it = 0; it < nt; it++) {
        int kt = kt0 + it, k0 = kt * 64;
        if (it + 1 < nt) load_kv((it + 1) & 1, kt + 1);
        asm volatile("cp.async.commit_group;" ::: "memory");
        asm volatile("cp.async.wait_group 1;" ::: "memory");
        __syncthreads();

        uint32_t kbase = sb + AT_ST + (uint32_t)(it & 1) * 16384u;
        uint32_t vbase = kbase + 8192u;

        // S = Q K^T
        float s[8][4];
#pragma unroll
        for (int nf = 0; nf < 8; nf++)
#pragma unroll
            for (int e = 0; e < 4; e++) s[nf][e] = 0.f;
#pragma unroll
        for (int kc = 0; kc < 4; kc++) {
            uint32_t kb[4][4];
#pragma unroll
            for (int t = 0; t < 4; t++)
                ldm4(kb[t], kbase + swz(t * 16 + brr, kc * 2 + bc16));
#pragma unroll
            for (int nf = 0; nf < 8; nf++)
                mma16816(s[nf], qf[kc], &kb[nf >> 1][(nf & 1) * 2]);
        }

        // scale + bias + window; online softmax
        int qr0 = q0 + w * 16 + gid, qr1 = qr0 + 8;
        float tm0 = -1e30f, tm1 = -1e30f;
#pragma unroll
        for (int nf = 0; nf < 8; nf++) {
            int j0 = k0 + nf * 8 + tig * 2;
#pragma unroll
            for (int e = 0; e < 4; e++) {
                int qi = (e & 2) ? qr1 : qr0;
                int rel = qi - (j0 + (e & 1));
                bool valid = (rel >= 0) && (rel < MAXL);
                float v = valid ? s[nf][e] * 0.125f + srelp[valid ? rel : 0] : -1e30f;
                s[nf][e] = v;
                if (e & 2) tm1 = fmaxf(tm1, v); else tm0 = fmaxf(tm0, v);
            }
        }
        tm0 = fmaxf(tm0, __shfl_xor_sync(0xffffffffu, tm0, 1));
        tm0 = fmaxf(tm0, __shfl_xor_sync(0xffffffffu, tm0, 2));
        tm1 = fmaxf(tm1, __shfl_xor_sync(0xffffffffu, tm1, 1));
        tm1 = fmaxf(tm1, __shfl_xor_sync(0xffffffffu, tm1, 2));
        float n0 = fmaxf(m0, tm0), n1 = fmaxf(m1, tm1);
        float a0 = __expf(m0 - n0), a1 = __expf(m1 - n1);
        m0 = n0; m1 = n1;
        float ts0 = 0.f, ts1 = 0.f;
#pragma unroll
        for (int nf = 0; nf < 8; nf++) {
            s[nf][0] = __expf(s[nf][0] - n0);
            s[nf][1] = __expf(s[nf][1] - n0);
            s[nf][2] = __expf(s[nf][2] - n1);
            s[nf][3] = __expf(s[nf][3] - n1);
            ts0 += s[nf][0] + s[nf][1];
            ts1 += s[nf][2] + s[nf][3];
        }
        ts0 += __shfl_xor_sync(0xffffffffu, ts0, 1);
        ts0 += __shfl_xor_sync(0xffffffffu, ts0, 2);
        ts1 += __shfl_xor_sync(0xffffffffu, ts1, 1);
        ts1 += __shfl_xor_sync(0xffffffffu, ts1, 2);
        l0 = l0 * a0 + ts0;
        l1 = l1 * a1 + ts1;
#pragma unroll
        for (int nf = 0; nf < 8; nf++) {
            o[nf][0] *= a0; o[nf][1] *= a0;
            o[nf][2] *= a1; o[nf][3] *= a1;
        }

        // P frags (C-layout -> A-layout)
        uint32_t pf[4][4];
#pragma unroll
        for (int kc = 0; kc < 4; kc++) {
            pf[kc][0] = packh2(s[2 * kc][0], s[2 * kc][1]);
            pf[kc][1] = packh2(s[2 * kc][2], s[2 * kc][3]);
            pf[kc][2] = packh2(s[2 * kc + 1][0], s[2 * kc + 1][1]);
            pf[kc][3] = packh2(s[2 * kc + 1][2], s[2 * kc + 1][3]);
        }

        // O += P V  (V^T frags via ldmatrix.trans)
#pragma unroll
        for (int kc = 0; kc < 4; kc++) {
            uint32_t vb[4][4];
#pragma unroll
            for (int vt = 0; vt < 4; vt++)
                ldm4t(vb[vt], vbase + swz(kc * 16 + vrr, vt * 2 + vc16));
#pragma unroll
            for (int nf = 0; nf < 8; nf++)
                mma16816(o[nf], pf[kc], &vb[nf >> 1][(nf & 1) * 2]);
        }
        __syncthreads();
    }

    float i0 = 1.0f / l0, i1 = 1.0f / l1;
    int r0 = q0 + w * 16 + gid;
#pragma unroll
    for (int nf = 0; nf < 8; nf++) {
        int col = h * DDIM + nf * 8 + tig * 2;
        *(__half2*)(outp + (size_t)(b * SEQ + r0) * EDIM + col) =
            __floats2half2_rn(o[nf][0] * i0, o[nf][1] * i0);
        *(__half2*)(outp + (size_t)(b * SEQ + r0 + 8) * EDIM + col) =
            __floats2half2_rn(o[nf][2] * i1, o[nf][3] * i1);
    }
}

// ======================= launch =======================
extern "C" void kernel_launch(void* const* d_in, const int* in_sizes, int n_in,
                              void* d_out, int out_size) {
    (void)in_sizes; (void)n_in; (void)out_size;
    const float* x    = (const float*)d_in[0];
    const float* relp = (const float*)d_in[1];
    const float* ipw  = (const float*)d_in[2];
    const float* ipb  = (const float*)d_in[3];
    const float* ow   = (const float*)d_in[4];
    const float* ob   = (const float*)d_in[5];
    const float* w1   = (const float*)d_in[6];
    const float* b1   = (const float*)d_in[7];
    const float* w2   = (const float*)d_in[8];
    const float* b2   = (const float*)d_in[9];
    const float* g1   = (const float*)d_in[10];
    const float* be1  = (const float*)d_in[11];
    const float* g2   = (const float*)d_in[12];
    const float* be2  = (const float*)d_in[13];
    float* out = (float*)d_out;

    float* p_x1;
    __half *p_xn, *p_qkv, *p_att, *p_xm, *p_h;
    __half *p_ipwh, *p_ipwl, *p_owh, *p_owl, *p_w1h, *p_w1l, *p_w2h, *p_w2l;
    cudaGetSymbolAddress((void**)&p_x1,  g_x1);
    cudaGetSymbolAddress((void**)&p_xn,  g_xn);
    cudaGetSymbolAddress((void**)&p_qkv, g_qkvh);
    cudaGetSymbolAddress((void**)&p_att, g_att);
    cudaGetSymbolAddress((void**)&p_xm,  g_xm);
    cudaGetSymbolAddress((void**)&p_h,   g_hb);
    cudaGetSymbolAddress((void**)&p_ipwh, g_ipwh); cudaGetSymbolAddress((void**)&p_ipwl, g_ipwl);
    cudaGetSymbolAddress((void**)&p_owh, g_owh);   cudaGetSymbolAddress((void**)&p_owl, g_owl);
    cudaGetSymbolAddress((void**)&p_w1h, g_w1h);   cudaGetSymbolAddress((void**)&p_w1l, g_w1l);
    cudaGetSymbolAddress((void**)&p_w2h, g_w2h);   cudaGetSymbolAddress((void**)&p_w2l, g_w2l);

    cudaFuncSetAttribute(gemm_mma<false, false, false>,
                         cudaFuncAttributeMaxDynamicSharedMemorySize, GSMEM);
    cudaFuncSetAttribute(gemm_mma<false, true, true>,
                         cudaFuncAttributeMaxDynamicSharedMemorySize, GSMEM);
    cudaFuncSetAttribute(gemm_mma<true, false, false>,
                         cudaFuncAttributeMaxDynamicSharedMemorySize, GSMEM);
    cudaFuncSetAttribute(attn_kernel,
                         cudaFuncAttributeMaxDynamicSharedMemorySize, AT_SMEM);

    // weight splits (fp16 hi/lo)
    split_kernel<<<3 * EDIM * EDIM / 1024, 256>>>((const float4*)ipw,
        (__half2*)p_ipwh, (__half2*)p_ipwl, 3 * EDIM * EDIM / 4);
    split_kernel<<<EDIM * EDIM / 1024, 256>>>((const float4*)ow,
        (__half2*)p_owh, (__half2*)p_owl, EDIM * EDIM / 4);
    split_kernel<<<4 * EDIM * EDIM / 1024, 256>>>((const float4*)w1,
        (__half2*)p_w1h, (__half2*)p_w1l, 4 * EDIM * EDIM / 4);
    split_kernel<<<4 * EDIM * EDIM / 1024, 256>>>((const float4*)w2,
        (__half2*)p_w2h, (__half2*)p_w2l, 4 * EDIM * EDIM / 4);

    // 1. ln1 -> xn fp16
    ln_kernel<<<ROWS, 256>>>(x, g1, be1, p_xn);
    // 2. qkv (fp16 out)
    gemm_mma<false, false, false><<<dim3(24, 32), 256, GSMEM>>>(
        p_xn, p_ipwh, p_ipwl, ipb, nullptr, nullptr, p_qkv, 3 * EDIM, EDIM);
    // 3. flash attention (fp16 out)
    attn_kernel<<<dim3(SEQ / 64, BATCH * HNUM), 128, AT_SMEM>>>(p_qkv, relp, p_att);
    // 4. x1 = x + att @ ow^T + ob (fp32 out)
    gemm_mma<false, true, true><<<dim3(8, 32), 256, GSMEM>>>(
        p_att, p_owh, p_owl, ob, x, p_x1, nullptr, EDIM, EDIM);
    // 5. ln2 -> xm fp16
    ln_kernel<<<ROWS, 256>>>(p_x1, g2, be2, p_xm);
    // 6. h = relu(xm @ w1^T + b1) fp16 out
    gemm_mma<true, false, false><<<dim3(32, 32), 256, GSMEM>>>(
        p_xm, p_w1h, p_w1l, b1, nullptr, nullptr, p_h, 4 * EDIM, EDIM);
    // 7. out = x1 + h @ w2^T + b2 (fp32 out)
    gemm_mma<false, true, true><<<dim3(8, 32), 256, GSMEM>>>(
        p_h, p_w2h, p_w2l, b2, p_x1, out, nullptr, EDIM, 4 * EDIM);
}

// round 10
// speedup vs baseline: 7.6151x; 1.0436x over previous
#include <cuda_runtime.h>
#include <cuda_fp16.h>
#include <math.h>
#include <stdint.h>

#define EDIM 1024
#define HNUM 16
#define DDIM 64
#define MAXL 512
#define BATCH 4
#define SEQ 1024
#define ROWS (BATCH * SEQ)   // 4096
#define EPSV 1e-5f

// ---------------- scratch ----------------
__device__ float g_x1[ROWS * EDIM];
__device__ __align__(16) __half g_xn  [ROWS * EDIM];
__device__ __align__(16) __half g_qkvh[ROWS * 3 * EDIM];
__device__ __align__(16) __half g_att [ROWS * EDIM];
__device__ __align__(16) __half g_xm  [ROWS * EDIM];
__device__ __align__(16) __half g_hb  [ROWS * 4 * EDIM];
__device__ __align__(16) __half g_ipwh[3 * EDIM * EDIM], g_ipwl[3 * EDIM * EDIM];
__device__ __align__(16) __half g_owh [EDIM * EDIM],     g_owl [EDIM * EDIM];
__device__ __align__(16) __half g_w1h [4 * EDIM * EDIM], g_w1l [4 * EDIM * EDIM];
__device__ __align__(16) __half g_w2h [4 * EDIM * EDIM], g_w2l [4 * EDIM * EDIM];

// ======================= helpers =======================
__device__ __forceinline__ uint32_t smem_u32(const void* p) {
    uint32_t a;
    asm("{ .reg .u64 t; cvta.to.shared.u64 t, %1; cvt.u32.u64 %0, t; }" : "=r"(a) : "l"(p));
    return a;
}
__device__ __forceinline__ void cpa16(uint32_t dst, const void* src) {
    asm volatile("cp.async.cg.shared.global [%0], [%1], 16;" :: "r"(dst), "l"(src));
}
__device__ __forceinline__ void ldm4(uint32_t* r, uint32_t addr) {
    asm volatile("ldmatrix.sync.aligned.m8n8.x4.shared.b16 {%0,%1,%2,%3}, [%4];"
                 : "=r"(r[0]), "=r"(r[1]), "=r"(r[2]), "=r"(r[3]) : "r"(addr));
}
__device__ __forceinline__ void ldm4t(uint32_t* r, uint32_t addr) {
    asm volatile("ldmatrix.sync.aligned.m8n8.x4.trans.shared.b16 {%0,%1,%2,%3}, [%4];"
                 : "=r"(r[0]), "=r"(r[1]), "=r"(r[2]), "=r"(r[3]) : "r"(addr));
}
__device__ __forceinline__ void mma16816(float* c, const uint32_t* a, const uint32_t* b) {
    asm volatile(
        "mma.sync.aligned.m16n8k16.row.col.f32.f16.f16.f32 "
        "{%0,%1,%2,%3}, {%4,%5,%6,%7}, {%8,%9}, {%0,%1,%2,%3};"
        : "+f"(c[0]), "+f"(c[1]), "+f"(c[2]), "+f"(c[3])
        : "r"(a[0]), "r"(a[1]), "r"(a[2]), "r"(a[3]), "r"(b[0]), "r"(b[1]));
}
__device__ __forceinline__ uint32_t packh2(float a, float b) {
    __half2 h = __floats2half2_rn(a, b);
    return *(uint32_t*)&h;
}
__device__ __forceinline__ uint32_t swz(int r, int c16) {
    return (uint32_t)(r * 128 + ((c16 ^ (r & 7)) << 4));
}

// ======================= fused weight split =======================
// One kernel splits all 4 weight matrices (fp32 -> fp16 hi/lo).
#define N4_IPW (3 * EDIM * EDIM / 4)
#define N4_OW  (EDIM * EDIM / 4)
#define N4_W1  (4 * EDIM * EDIM / 4)
#define N4_W2  (4 * EDIM * EDIM / 4)
#define N4_TOT (N4_IPW + N4_OW + N4_W1 + N4_W2)

__global__ void split_all_kernel(const float4* __restrict__ ipw,
                                 const float4* __restrict__ ow,
                                 const float4* __restrict__ w1,
                                 const float4* __restrict__ w2,
                                 __half2* __restrict__ ipwh, __half2* __restrict__ ipwl,
                                 __half2* __restrict__ owh,  __half2* __restrict__ owl,
                                 __half2* __restrict__ w1h,  __half2* __restrict__ w1l,
                                 __half2* __restrict__ w2h,  __half2* __restrict__ w2l) {
    int i = blockIdx.x * 256 + threadIdx.x;
    if (i >= N4_TOT) return;
    const float4* src;
    __half2 *hi, *lo;
    int j = i;
    if (j < N4_IPW) { src = ipw; hi = ipwh; lo = ipwl; }
    else if ((j -= N4_IPW) < N4_OW) { src = ow; hi = owh; lo = owl; }
    else if ((j -= N4_OW) < N4_W1)  { src = w1; hi = w1h; lo = w1l; }
    else { j -= N4_W1; src = w2; hi = w2h; lo = w2l; }
    float4 f = src[j];
    float h0 = __half2float(__float2half_rn(f.x));
    float h1 = __half2float(__float2half_rn(f.y));
    float h2 = __half2float(__float2half_rn(f.z));
    float h3 = __half2float(__float2half_rn(f.w));
    hi[2 * j]     = __floats2half2_rn(h0, h1);
    hi[2 * j + 1] = __floats2half2_rn(h2, h3);
    lo[2 * j]     = __floats2half2_rn(f.x - h0, f.y - h1);
    lo[2 * j + 1] = __floats2half2_rn(f.z - h2, f.w - h3);
}

// ======================= LayerNorm (fp32 -> fp16) =======================
__global__ void ln_kernel(const float* __restrict__ x,
                          const float* __restrict__ g,
                          const float* __restrict__ b,
                          __half* __restrict__ o) {
    int row = blockIdx.x;
    int tid = threadIdx.x;
    const float4* xr = (const float4*)(x + (size_t)row * EDIM);
    float4 v = xr[tid];
    float s  = v.x + v.y + v.z + v.w;
    float ss = v.x * v.x + v.y * v.y + v.z * v.z + v.w * v.w;
#pragma unroll
    for (int of = 16; of > 0; of >>= 1) {
        s  += __shfl_xor_sync(0xffffffffu, s,  of);
        ss += __shfl_xor_sync(0xffffffffu, ss, of);
    }
    __shared__ float rs[8], rss[8];
    __shared__ float s_mu, s_rstd;
    if ((tid & 31) == 0) { rs[tid >> 5] = s; rss[tid >> 5] = ss; }
    __syncthreads();
    if (tid == 0) {
        float S = 0.f, SS = 0.f;
#pragma unroll
        for (int i = 0; i < 8; i++) { S += rs[i]; SS += rss[i]; }
        float mu = S * (1.0f / EDIM);
        float var = SS * (1.0f / EDIM) - mu * mu;
        s_mu = mu; s_rstd = rsqrtf(var + EPSV);
    }
    __syncthreads();
    float mu = s_mu, rstd = s_rstd;
    float4 gg = ((const float4*)g)[tid];
    float4 bb = ((const float4*)b)[tid];
    __half2* po = (__half2*)(o + (size_t)row * EDIM);
    po[2 * tid]     = __floats2half2_rn((v.x - mu) * rstd * gg.x + bb.x,
                                        (v.y - mu) * rstd * gg.y + bb.y);
    po[2 * tid + 1] = __floats2half2_rn((v.z - mu) * rstd * gg.z + bb.z,
                                        (v.w - mu) * rstd * gg.w + bb.w);
}

// ======================= fp16 2-term GEMM =======================
// BM=128 BN=128 BK=64, 256 thr, 8 warps (2M x 4N); 2 CTAs/SM for overlap.
#define TIL 16384u
#define STG (3u * TIL)
#define GSMEM (2u * STG)           // 98304

template <bool RELU, bool RES, bool OUTF32>
__global__ void __launch_bounds__(256, 2)
gemm_mma(const __half* __restrict__ A,
         const __half* __restrict__ Bh, const __half* __restrict__ Bl,
         const float* __restrict__ bias, const float* __restrict__ res,
         float* __restrict__ C, __half* __restrict__ Ch, int Nc, int K) {
    extern __shared__ char sm[];
    uint32_t sb = smem_u32(sm);
    int tid = threadIdx.x;
    int wid = tid >> 5, lane = tid & 31;
    int wm = wid & 1, wn = wid >> 1;
    int brow = blockIdx.y * 128, bcol = blockIdx.x * 128;

    float acc[4][4][4];
#pragma unroll
    for (int i = 0; i < 4; i++)
#pragma unroll
        for (int j = 0; j < 4; j++)
#pragma unroll
            for (int k = 0; k < 4; k++) acc[i][j][k] = 0.f;

    int nchunk = K >> 6;
    auto load_stage = [&](int st, int k0) {
        uint32_t base = sb + (uint32_t)st * STG;
#pragma unroll
        for (int i = 0; i < 12; i++) {
            int idx = tid + i * 256;
            int part = idx >> 10;
            int r = (idx & 1023) >> 3, c16 = idx & 7;
            uint32_t d = base + part * TIL + swz(r, c16);
            const __half* src = (part == 0) ? A + (size_t)(brow + r) * K + k0 + c16 * 8
                              : (part == 1) ? Bh + (size_t)(bcol + r) * K + k0 + c16 * 8
                                            : Bl + (size_t)(bcol + r) * K + k0 + c16 * 8;
            cpa16(d, src);
        }
    };

    load_stage(0, 0);
    asm volatile("cp.async.commit_group;" ::: "memory");

    int l15 = lane & 15;
    int ac16 = (lane & 16) ? 1 : 0;
    int brr = (lane & 7) + ((lane & 16) ? 8 : 0);
    int bc16 = (lane & 8) ? 1 : 0;

    for (int ch = 0; ch < nchunk; ch++) {
        if (ch + 1 < nchunk) load_stage((ch + 1) & 1, (ch + 1) * 64);
        asm volatile("cp.async.commit_group;" ::: "memory");
        asm volatile("cp.async.wait_group 1;" ::: "memory");
        __syncthreads();

        uint32_t base = sb + (uint32_t)(ch & 1) * STG;
#pragma unroll
        for (int kc = 0; kc < 4; kc++) {
            uint32_t bh[2][4], bl[2][4];
#pragma unroll
            for (int p = 0; p < 2; p++) {
                uint32_t ro = swz(wn * 32 + p * 16 + brr, kc * 2 + bc16);
                ldm4(bh[p], base + TIL + ro);
                ldm4(bl[p], base + 2 * TIL + ro);
            }
#pragma unroll
            for (int mf = 0; mf < 4; mf++) {
                uint32_t a[4];
                ldm4(a, base + swz(wm * 64 + mf * 16 + l15, kc * 2 + ac16));
#pragma unroll
                for (int nf = 0; nf < 4; nf++) {
                    mma16816(acc[mf][nf], a, &bh[nf >> 1][(nf & 1) * 2]);
                    mma16816(acc[mf][nf], a, &bl[nf >> 1][(nf & 1) * 2]);
                }
            }
        }
        __syncthreads();
    }

    int gid = lane >> 2, tig = lane & 3;
#pragma unroll
    for (int mf = 0; mf < 4; mf++) {
#pragma unroll
        for (int nf = 0; nf < 4; nf++) {
            int col = bcol + wn * 32 + nf * 8 + tig * 2;
            float b0 = bias[col], b1 = bias[col + 1];
#pragma unroll
            for (int hr = 0; hr < 2; hr++) {
                int row = brow + wm * 64 + mf * 16 + gid + hr * 8;
                float v0 = acc[mf][nf][hr * 2 + 0] + b0;
                float v1 = acc[mf][nf][hr * 2 + 1] + b1;
                if (RELU) { v0 = fmaxf(v0, 0.f); v1 = fmaxf(v1, 0.f); }
                if (RES) {
                    float2 r2 = *(const float2*)(res + (size_t)row * Nc + col);
                    v0 += r2.x; v1 += r2.y;
                }
                if (OUTF32) {
                    float2 o2; o2.x = v0; o2.y = v1;
                    *(float2*)(C + (size_t)row * Nc + col) = o2;
                } else {
                    *(__half2*)(Ch + (size_t)row * Nc + col) = __floats2half2_rn(v0, v1);
                }
            }
        }
    }
}

// ======================= flash attention (mma.sync fp16) =======================
// Block: 128 queries x (b,h); 8 warps of 16 queries. Key tiles of 64, dbl-buffered.
#define AT_SQ   0u
#define AT_RP   16384u             // Q tile 128*128B
#define AT_ST   18432u             // + relp 2KB
#define AT_SMEM (18432u + 2u * 16384u)   // + 2 stages of [K 8KB | V 8KB]

__global__ void __launch_bounds__(256)
attn_kernel(const __half* __restrict__ qkv, const float* __restrict__ relp,
            __half* __restrict__ outp) {
    extern __shared__ char sm[];
    uint32_t sb = smem_u32(sm);
    float* srelp = (float*)(sm + AT_RP);
    int tid = threadIdx.x;
    int w = tid >> 5, lane = tid & 31;
    int gid = lane >> 2, tig = lane & 3;
    int qt = blockIdx.x, q0 = qt * 128;
    int bh = blockIdx.y;
    int b = bh >> 4, h = bh & 15;

#pragma unroll
    for (int i = 0; i < 2; i++) srelp[tid + i * 256] = relp[h * MAXL + tid + i * 256];
#pragma unroll
    for (int i = 0; i < 4; i++) {
        int idx = tid + i * 256;              // 1024 chunks
        int r = idx >> 3, c16 = idx & 7;
        uint4 q4 = *(const uint4*)(qkv + (size_t)(b * SEQ + q0 + r) * 3 * EDIM +
                                   h * DDIM + c16 * 8);
        *(uint4*)(sm + AT_SQ + swz(r, c16)) = q4;
    }
    __syncthreads();

    uint32_t qf[4][4];
    int l15 = lane & 15;
    int ac16 = (lane & 16) ? 1 : 0;
#pragma unroll
    for (int kc = 0; kc < 4; kc++)
        ldm4(qf[kc], sb + AT_SQ + swz(w * 16 + l15, kc * 2 + ac16));

    float o[8][4];
#pragma unroll
    for (int nf = 0; nf < 8; nf++)
#pragma unroll
        for (int e = 0; e < 4; e++) o[nf][e] = 0.f;
    float m0 = -1e30f, m1 = -1e30f, l0 = 0.f, l1 = 0.f;

    int ktlo = 2 * qt - 8; if (ktlo < 0) ktlo = 0;
    int kthi = 2 * qt + 1;
    int nt = kthi - ktlo + 1;
    int qlo = q0 + w * 16, qhi = qlo + 15;   // this warp's query range

    auto load_kv = [&](int st, int kt) {
        uint32_t base = sb + AT_ST + (uint32_t)st * 16384u;
        int k0 = kt * 64;
#pragma unroll
        for (int i = 0; i < 4; i++) {
            int idx = tid + i * 256;          // 0..1023; 512 K then 512 V
            int part = idx >> 9;
            int r = (idx & 511) >> 3, c16 = idx & 7;
            const __half* src = qkv + (size_t)(b * SEQ + k0 + r) * 3 * EDIM +
                                (part ? 2 * EDIM : EDIM) + h * DDIM + c16 * 8;
            cpa16(base + part * 8192u + swz(r, c16), src);
        }
    };

    load_kv(0, ktlo);
    asm volatile("cp.async.commit_group;" ::: "memory");

    int brr = (lane & 7) + ((lane & 16) ? 8 : 0);
    int bc16 = (lane & 8) ? 1 : 0;
    int vrr = (lane & 7) + ((lane & 8) ? 8 : 0);
    int vc16 = (lane & 16) ? 1 : 0;

    for (int it = 0; it < nt; it++) {
        int kt = ktlo + it, k0 = kt * 64;
        if (it + 1 < nt) load_kv((it + 1) & 1, kt + 1);
        asm volatile("cp.async.commit_group;" ::: "memory");
        asm volatile("cp.async.wait_group 1;" ::: "memory");
        __syncthreads();

        // warp-level tile skip: no key in this tile intersects warp's window
        bool active = (k0 <= qhi) && (k0 + 63 >= qlo - (MAXL - 1));
        if (active) {
            uint32_t kbase = sb + AT_ST + (uint32_t)(it & 1) * 16384u;
            uint32_t vbase = kbase + 8192u;

            float s[8][4];
#pragma unroll
            for (int nf = 0; nf < 8; nf++)
#pragma unroll
                for (int e = 0; e < 4; e++) s[nf][e] = 0.f;
#pragma unroll
            for (int kc = 0; kc < 4; kc++) {
                uint32_t kb[4][4];
#pragma unroll
                for (int t = 0; t < 4; t++)
                    ldm4(kb[t], kbase + swz(t * 16 + brr, kc * 2 + bc16));
#pragma unroll
                for (int nf = 0; nf < 8; nf++)
                    mma16816(s[nf], qf[kc], &kb[nf >> 1][(nf & 1) * 2]);
            }

            int qr0 = qlo + gid, qr1 = qr0 + 8;
            float tm0 = -1e30f, tm1 = -1e30f;
#pragma unroll
            for (int nf = 0; nf < 8; nf++) {
                int j0 = k0 + nf * 8 + tig * 2;
#pragma unroll
                for (int e = 0; e < 4; e++) {
                    int qi = (e & 2) ? qr1 : qr0;
                    int rel = qi - (j0 + (e & 1));
                    bool valid = (rel >= 0) && (rel < MAXL);
                    float v = valid ? s[nf][e] * 0.125f + srelp[valid ? rel : 0] : -1e30f;
                    s[nf][e] = v;
                    if (e & 2) tm1 = fmaxf(tm1, v); else tm0 = fmaxf(tm0, v);
                }
            }
            tm0 = fmaxf(tm0, __shfl_xor_sync(0xffffffffu, tm0, 1));
            tm0 = fmaxf(tm0, __shfl_xor_sync(0xffffffffu, tm0, 2));
            tm1 = fmaxf(tm1, __shfl_xor_sync(0xffffffffu, tm1, 1));
            tm1 = fmaxf(tm1, __shfl_xor_sync(0xffffffffu, tm1, 2));
            float n0 = fmaxf(m0, tm0), n1 = fmaxf(m1, tm1);
            float a0 = __expf(m0 - n0), a1 = __expf(m1 - n1);
            m0 = n0; m1 = n1;
            float ts0 = 0.f, ts1 = 0.f;
#pragma unroll
            for (int nf = 0; nf < 8; nf++) {
                s[nf][0] = __expf(s[nf][0] - n0);
                s[nf][1] = __expf(s[nf][1] - n0);
                s[nf][2] = __expf(s[nf][2] - n1);
                s[nf][3] = __expf(s[nf][3] - n1);
                ts0 += s[nf][0] + s[nf][1];
                ts1 += s[nf][2] + s[nf][3];
            }
            ts0 += __shfl_xor_sync(0xffffffffu, ts0, 1);
            ts0 += __shfl_xor_sync(0xffffffffu, ts0, 2);
            ts1 += __shfl_xor_sync(0xffffffffu, ts1, 1);
            ts1 += __shfl_xor_sync(0xffffffffu, ts1, 2);
            l0 = l0 * a0 + ts0;
            l1 = l1 * a1 + ts1;
#pragma unroll
            for (int nf = 0; nf < 8; nf++) {
                o[nf][0] *= a0; o[nf][1] *= a0;
                o[nf][2] *= a1; o[nf][3] *= a1;
            }

            uint32_t pf[4][4];
#pragma unroll
            for (int kc = 0; kc < 4; kc++) {
                pf[kc][0] = packh2(s[2 * kc][0], s[2 * kc][1]);
                pf[kc][1] = packh2(s[2 * kc][2], s[2 * kc][3]);
                pf[kc][2] = packh2(s[2 * kc + 1][0], s[2 * kc + 1][1]);
                pf[kc][3] = packh2(s[2 * kc + 1][2], s[2 * kc + 1][3]);
            }
#pragma unroll
            for (int kc = 0; kc < 4; kc++) {
                uint32_t vb[4][4];
#pragma unroll
                for (int vt = 0; vt < 4; vt++)
                    ldm4t(vb[vt], vbase + swz(kc * 16 + vrr, vt * 2 + vc16));
#pragma unroll
                for (int nf = 0; nf < 8; nf++)
                    mma16816(o[nf], pf[kc], &vb[nf >> 1][(nf & 1) * 2]);
            }
        }
        __syncthreads();
    }

    float i0 = 1.0f / l0, i1 = 1.0f / l1;
    int r0 = qlo + gid;
#pragma unroll
    for (int nf = 0; nf < 8; nf++) {
        int col = h * DDIM + nf * 8 + tig * 2;
        *(__half2*)(outp + (size_t)(b * SEQ + r0) * EDIM + col) =
            __floats2half2_rn(o[nf][0] * i0, o[nf][1] * i0);
        *(__half2*)(outp + (size_t)(b * SEQ + r0 + 8) * EDIM + col) =
            __floats2half2_rn(o[nf][2] * i1, o[nf][3] * i1);
    }
}

// ======================= launch =======================
extern "C" void kernel_launch(void* const* d_in, const int* in_sizes, int n_in,
                              void* d_out, int out_size) {
    (void)in_sizes; (void)n_in; (void)out_size;
    const float* x    = (const float*)d_in[0];
    const float* relp = (const float*)d_in[1];
    const float* ipw  = (const float*)d_in[2];
    const float* ipb  = (const float*)d_in[3];
    const float* ow   = (const float*)d_in[4];
    const float* ob   = (const float*)d_in[5];
    const float* w1   = (const float*)d_in[6];
    const float* b1   = (const float*)d_in[7];
    const float* w2   = (const float*)d_in[8];
    const float* b2   = (const float*)d_in[9];
    const float* g1   = (const float*)d_in[10];
    const float* be1  = (const float*)d_in[11];
    const float* g2   = (const float*)d_in[12];
    const float* be2  = (const float*)d_in[13];
    float* out = (float*)d_out;

    float* p_x1;
    __half *p_xn, *p_qkv, *p_att, *p_xm, *p_h;
    __half *p_ipwh, *p_ipwl, *p_owh, *p_owl, *p_w1h, *p_w1l, *p_w2h, *p_w2l;
    cudaGetSymbolAddress((void**)&p_x1,  g_x1);
    cudaGetSymbolAddress((void**)&p_xn,  g_xn);
    cudaGetSymbolAddress((void**)&p_qkv, g_qkvh);
    cudaGetSymbolAddress((void**)&p_att, g_att);
    cudaGetSymbolAddress((void**)&p_xm,  g_xm);
    cudaGetSymbolAddress((void**)&p_h,   g_hb);
    cudaGetSymbolAddress((void**)&p_ipwh, g_ipwh); cudaGetSymbolAddress((void**)&p_ipwl, g_ipwl);
    cudaGetSymbolAddress((void**)&p_owh, g_owh);   cudaGetSymbolAddress((void**)&p_owl, g_owl);
    cudaGetSymbolAddress((void**)&p_w1h, g_w1h);   cudaGetSymbolAddress((void**)&p_w1l, g_w1l);
    cudaGetSymbolAddress((void**)&p_w2h, g_w2h);   cudaGetSymbolAddress((void**)&p_w2l, g_w2l);

    cudaFuncSetAttribute(gemm_mma<false, false, false>,
                         cudaFuncAttributeMaxDynamicSharedMemorySize, GSMEM);
    cudaFuncSetAttribute(gemm_mma<false, true, true>,
                         cudaFuncAttributeMaxDynamicSharedMemorySize, GSMEM);
    cudaFuncSetAttribute(gemm_mma<true, false, false>,
                         cudaFuncAttributeMaxDynamicSharedMemorySize, GSMEM);
    cudaFuncSetAttribute(attn_kernel,
                         cudaFuncAttributeMaxDynamicSharedMemorySize, AT_SMEM);

    // 0. fused weight split (fp16 hi/lo)
    split_all_kernel<<<(N4_TOT + 255) / 256, 256>>>(
        (const float4*)ipw, (const float4*)ow, (const float4*)w1, (const float4*)w2,
        (__half2*)p_ipwh, (__half2*)p_ipwl, (__half2*)p_owh, (__half2*)p_owl,
        (__half2*)p_w1h, (__half2*)p_w1l, (__half2*)p_w2h, (__half2*)p_w2l);

    // 1. ln1 -> xn fp16
    ln_kernel<<<ROWS, 256>>>(x, g1, be1, p_xn);
    // 2. qkv (fp16 out)
    gemm_mma<false, false, false><<<dim3(24, 32), 256, GSMEM>>>(
        p_xn, p_ipwh, p_ipwl, ipb, nullptr, nullptr, p_qkv, 3 * EDIM, EDIM);
    // 3. flash attention (fp16 out)
    attn_kernel<<<dim3(SEQ / 128, BATCH * HNUM), 256, AT_SMEM>>>(p_qkv, relp, p_att);
    // 4. x1 = x + att @ ow^T + ob (fp32 out)
    gemm_mma<false, true, true><<<dim3(8, 32), 256, GSMEM>>>(
        p_att, p_owh, p_owl, ob, x, p_x1, nullptr, EDIM, EDIM);
    // 5. ln2 -> xm fp16
    ln_kernel<<<ROWS, 256>>>(p_x1, g2, be2, p_xm);
    // 6. h = relu(xm @ w1^T + b1) fp16 out
    gemm_mma<true, false, false><<<dim3(32, 32), 256, GSMEM>>>(
        p_xm, p_w1h, p_w1l, b1, nullptr, nullptr, p_h, 4 * EDIM, EDIM);
    // 7. out = x1 + h @ w2^T + b2 (fp32 out)
    gemm_mma<false, true, true><<<dim3(8, 32), 256, GSMEM>>>(
        p_h, p_w2h, p_w2l, b2, p_x1, out, nullptr, EDIM, 4 * EDIM);
}

// round 11
// speedup vs baseline: 12.4550x; 1.6356x over previous
#include <cuda_runtime.h>
#include <cuda_fp16.h>
#include <math.h>
#include <stdint.h>

#define EDIM 1024
#define HNUM 16
#define DDIM 64
#define MAXL 512
#define BATCH 4
#define SEQ 1024
#define ROWS (BATCH * SEQ)   // 4096
#define EPSV 1e-5f

// ---------------- scratch ----------------
__device__ float g_x1[ROWS * EDIM];
__device__ __align__(16) __half g_xn  [ROWS * EDIM];
__device__ __align__(16) __half g_qkvh[ROWS * 3 * EDIM];
__device__ __align__(16) __half g_att [ROWS * EDIM];
__device__ __align__(16) __half g_xm  [ROWS * EDIM];
__device__ __align__(16) __half g_hb  [ROWS * 4 * EDIM];
__device__ __align__(16) __half g_ipw16[3 * EDIM * EDIM];
__device__ __align__(16) __half g_ow16 [EDIM * EDIM];
__device__ __align__(16) __half g_w116 [4 * EDIM * EDIM];
__device__ __align__(16) __half g_w216 [4 * EDIM * EDIM];

// ======================= helpers =======================
__device__ __forceinline__ uint32_t smem_u32(const void* p) {
    uint32_t a;
    asm("{ .reg .u64 t; cvta.to.shared.u64 t, %1; cvt.u32.u64 %0, t; }" : "=r"(a) : "l"(p));
    return a;
}
__device__ __forceinline__ void cpa16(uint32_t dst, const void* src) {
    asm volatile("cp.async.cg.shared.global [%0], [%1], 16;" :: "r"(dst), "l"(src));
}
__device__ __forceinline__ void ldm4(uint32_t* r, uint32_t addr) {
    asm volatile("ldmatrix.sync.aligned.m8n8.x4.shared.b16 {%0,%1,%2,%3}, [%4];"
                 : "=r"(r[0]), "=r"(r[1]), "=r"(r[2]), "=r"(r[3]) : "r"(addr));
}
__device__ __forceinline__ void ldm4t(uint32_t* r, uint32_t addr) {
    asm volatile("ldmatrix.sync.aligned.m8n8.x4.trans.shared.b16 {%0,%1,%2,%3}, [%4];"
                 : "=r"(r[0]), "=r"(r[1]), "=r"(r[2]), "=r"(r[3]) : "r"(addr));
}
__device__ __forceinline__ void mma16816(float* c, const uint32_t* a, const uint32_t* b) {
    asm volatile(
        "mma.sync.aligned.m16n8k16.row.col.f32.f16.f16.f32 "
        "{%0,%1,%2,%3}, {%4,%5,%6,%7}, {%8,%9}, {%0,%1,%2,%3};"
        : "+f"(c[0]), "+f"(c[1]), "+f"(c[2]), "+f"(c[3])
        : "r"(a[0]), "r"(a[1]), "r"(a[2]), "r"(a[3]), "r"(b[0]), "r"(b[1]));
}
__device__ __forceinline__ uint32_t packh2(float a, float b) {
    __half2 h = __floats2half2_rn(a, b);
    return *(uint32_t*)&h;
}
__device__ __forceinline__ uint32_t swz(int r, int c16) {
    return (uint32_t)(r * 128 + ((c16 ^ (r & 7)) << 4));
}

// ======================= fused weight convert fp32->fp16 =======================
#define N4_IPW (3 * EDIM * EDIM / 4)
#define N4_OW  (EDIM * EDIM / 4)
#define N4_W1  (4 * EDIM * EDIM / 4)
#define N4_W2  (4 * EDIM * EDIM / 4)
#define N4_TOT (N4_IPW + N4_OW + N4_W1 + N4_W2)

__global__ void convert_all_kernel(const float4* __restrict__ ipw,
                                   const float4* __restrict__ ow,
                                   const float4* __restrict__ w1,
                                   const float4* __restrict__ w2,
                                   __half2* __restrict__ ipwo, __half2* __restrict__ owo,
                                   __half2* __restrict__ w1o,  __half2* __restrict__ w2o) {
    int i = blockIdx.x * 256 + threadIdx.x;
    if (i >= N4_TOT) return;
    const float4* src;
    __half2* dst;
    int j = i;
    if (j < N4_IPW) { src = ipw; dst = ipwo; }
    else if ((j -= N4_IPW) < N4_OW) { src = ow; dst = owo; }
    else if ((j -= N4_OW) < N4_W1)  { src = w1; dst = w1o; }
    else { j -= N4_W1; src = w2; dst = w2o; }
    float4 f = src[j];
    dst[2 * j]     = __floats2half2_rn(f.x, f.y);
    dst[2 * j + 1] = __floats2half2_rn(f.z, f.w);
}

// ======================= LayerNorm (fp32 -> fp16) =======================
__global__ void ln_kernel(const float* __restrict__ x,
                          const float* __restrict__ g,
                          const float* __restrict__ b,
                          __half* __restrict__ o) {
    int row = blockIdx.x;
    int tid = threadIdx.x;
    const float4* xr = (const float4*)(x + (size_t)row * EDIM);
    float4 v = xr[tid];
    float s  = v.x + v.y + v.z + v.w;
    float ss = v.x * v.x + v.y * v.y + v.z * v.z + v.w * v.w;
#pragma unroll
    for (int of = 16; of > 0; of >>= 1) {
        s  += __shfl_xor_sync(0xffffffffu, s,  of);
        ss += __shfl_xor_sync(0xffffffffu, ss, of);
    }
    __shared__ float rs[8], rss[8];
    __shared__ float s_mu, s_rstd;
    if ((tid & 31) == 0) { rs[tid >> 5] = s; rss[tid >> 5] = ss; }
    __syncthreads();
    if (tid == 0) {
        float S = 0.f, SS = 0.f;
#pragma unroll
        for (int i = 0; i < 8; i++) { S += rs[i]; SS += rss[i]; }
        float mu = S * (1.0f / EDIM);
        float var = SS * (1.0f / EDIM) - mu * mu;
        s_mu = mu; s_rstd = rsqrtf(var + EPSV);
    }
    __syncthreads();
    float mu = s_mu, rstd = s_rstd;
    float4 gg = ((const float4*)g)[tid];
    float4 bb = ((const float4*)b)[tid];
    __half2* po = (__half2*)(o + (size_t)row * EDIM);
    po[2 * tid]     = __floats2half2_rn((v.x - mu) * rstd * gg.x + bb.x,
                                        (v.y - mu) * rstd * gg.y + bb.y);
    po[2 * tid + 1] = __floats2half2_rn((v.z - mu) * rstd * gg.z + bb.z,
                                        (v.w - mu) * rstd * gg.w + bb.w);
}

// ======================= fp16 GEMM, 3-stage pipeline =======================
// C[4096,Nc] = A[4096,K] @ B[Nc,K]^T, all fp16 operands, fp32 accum.
// BM=128 BN=128 BK=64, 256 thr, 8 warps (2M x 4N), 2 CTAs/SM.
#define TIL 16384u
#define STG (2u * TIL)             // A, B
#define GSMEM (3u * STG)           // 3 stages = 98304

template <bool RELU, bool RES, bool OUTF32>
__global__ void __launch_bounds__(256, 2)
gemm_mma(const __half* __restrict__ A, const __half* __restrict__ B,
         const float* __restrict__ bias, const float* __restrict__ res,
         float* __restrict__ C, __half* __restrict__ Ch, int Nc, int K) {
    extern __shared__ char sm[];
    uint32_t sb = smem_u32(sm);
    int tid = threadIdx.x;
    int wid = tid >> 5, lane = tid & 31;
    int wm = wid & 1, wn = wid >> 1;
    int brow = blockIdx.y * 128, bcol = blockIdx.x * 128;

    float acc[4][4][4];
#pragma unroll
    for (int i = 0; i < 4; i++)
#pragma unroll
        for (int j = 0; j < 4; j++)
#pragma unroll
            for (int k = 0; k < 4; k++) acc[i][j][k] = 0.f;

    int nchunk = K >> 6;
    auto load_stage = [&](int st, int k0) {
        uint32_t base = sb + (uint32_t)st * STG;
#pragma unroll
        for (int i = 0; i < 8; i++) {
            int idx = tid + i * 256;          // 0..2047
            int part = idx >> 10;             // 0=A 1=B
            int r = (idx & 1023) >> 3, c16 = idx & 7;
            uint32_t d = base + part * TIL + swz(r, c16);
            const __half* src = (part == 0)
                ? A + (size_t)(brow + r) * K + k0 + c16 * 8
                : B + (size_t)(bcol + r) * K + k0 + c16 * 8;
            cpa16(d, src);
        }
    };

    load_stage(0, 0);
    asm volatile("cp.async.commit_group;" ::: "memory");
    if (nchunk > 1) load_stage(1, 64);
    asm volatile("cp.async.commit_group;" ::: "memory");

    int l15 = lane & 15;
    int ac16 = (lane & 16) ? 1 : 0;
    int brr = (lane & 7) + ((lane & 16) ? 8 : 0);
    int bc16 = (lane & 8) ? 1 : 0;

    int stage = 0;
    for (int ch = 0; ch < nchunk; ch++) {
        asm volatile("cp.async.wait_group 1;" ::: "memory");
        __syncthreads();                       // stage `stage` ready; prior compute done
        if (ch + 2 < nchunk) {
            int ns = stage + 2; if (ns >= 3) ns -= 3;
            load_stage(ns, (ch + 2) * 64);
        }
        asm volatile("cp.async.commit_group;" ::: "memory");

        uint32_t base = sb + (uint32_t)stage * STG;
#pragma unroll
        for (int kc = 0; kc < 4; kc++) {
            uint32_t kb[2][4];
#pragma unroll
            for (int p = 0; p < 2; p++)
                ldm4(kb[p], base + TIL + swz(wn * 32 + p * 16 + brr, kc * 2 + bc16));
#pragma unroll
            for (int mf = 0; mf < 4; mf++) {
                uint32_t a[4];
                ldm4(a, base + swz(wm * 64 + mf * 16 + l15, kc * 2 + ac16));
#pragma unroll
                for (int nf = 0; nf < 4; nf++)
                    mma16816(acc[mf][nf], a, &kb[nf >> 1][(nf & 1) * 2]);
            }
        }
        if (++stage >= 3) stage = 0;
    }
    __syncthreads();

    int gid = lane >> 2, tig = lane & 3;
#pragma unroll
    for (int mf = 0; mf < 4; mf++) {
#pragma unroll
        for (int nf = 0; nf < 4; nf++) {
            int col = bcol + wn * 32 + nf * 8 + tig * 2;
            float b0 = bias[col], b1 = bias[col + 1];
#pragma unroll
            for (int hr = 0; hr < 2; hr++) {
                int row = brow + wm * 64 + mf * 16 + gid + hr * 8;
                float v0 = acc[mf][nf][hr * 2 + 0] + b0;
                float v1 = acc[mf][nf][hr * 2 + 1] + b1;
                if (RELU) { v0 = fmaxf(v0, 0.f); v1 = fmaxf(v1, 0.f); }
                if (RES) {
                    float2 r2 = *(const float2*)(res + (size_t)row * Nc + col);
                    v0 += r2.x; v1 += r2.y;
                }
                if (OUTF32) {
                    float2 o2; o2.x = v0; o2.y = v1;
                    *(float2*)(C + (size_t)row * Nc + col) = o2;
                } else {
                    *(__half2*)(Ch + (size_t)row * Nc + col) = __floats2half2_rn(v0, v1);
                }
            }
        }
    }
}

// ======================= flash attention (mma.sync fp16) =======================
// Block: 128 queries x (b,h); 8 warps of 16 queries. Key tiles of 64, dbl-buffered.
#define AT_SQ   0u
#define AT_RP   16384u
#define AT_ST   18432u
#define AT_SMEM (18432u + 2u * 16384u)

__global__ void __launch_bounds__(256)
attn_kernel(const __half* __restrict__ qkv, const float* __restrict__ relp,
            __half* __restrict__ outp) {
    extern __shared__ char sm[];
    uint32_t sb = smem_u32(sm);
    float* srelp = (float*)(sm + AT_RP);
    int tid = threadIdx.x;
    int w = tid >> 5, lane = tid & 31;
    int gid = lane >> 2, tig = lane & 3;
    int qt = blockIdx.x, q0 = qt * 128;
    int bh = blockIdx.y;
    int b = bh >> 4, h = bh & 15;

#pragma unroll
    for (int i = 0; i < 2; i++) srelp[tid + i * 256] = relp[h * MAXL + tid + i * 256];
#pragma unroll
    for (int i = 0; i < 4; i++) {
        int idx = tid + i * 256;
        int r = idx >> 3, c16 = idx & 7;
        uint4 q4 = *(const uint4*)(qkv + (size_t)(b * SEQ + q0 + r) * 3 * EDIM +
                                   h * DDIM + c16 * 8);
        *(uint4*)(sm + AT_SQ + swz(r, c16)) = q4;
    }
    __syncthreads();

    uint32_t qf[4][4];
    int l15 = lane & 15;
    int ac16 = (lane & 16) ? 1 : 0;
#pragma unroll
    for (int kc = 0; kc < 4; kc++)
        ldm4(qf[kc], sb + AT_SQ + swz(w * 16 + l15, kc * 2 + ac16));

    float o[8][4];
#pragma unroll
    for (int nf = 0; nf < 8; nf++)
#pragma unroll
        for (int e = 0; e < 4; e++) o[nf][e] = 0.f;
    float m0 = -1e30f, m1 = -1e30f, l0 = 0.f, l1 = 0.f;

    int ktlo = 2 * qt - 8; if (ktlo < 0) ktlo = 0;
    int kthi = 2 * qt + 1;
    int nt = kthi - ktlo + 1;
    int qlo = q0 + w * 16, qhi = qlo + 15;

    auto load_kv = [&](int st, int kt) {
        uint32_t base = sb + AT_ST + (uint32_t)st * 16384u;
        int k0 = kt * 64;
#pragma unroll
        for (int i = 0; i < 4; i++) {
            int idx = tid + i * 256;
            int part = idx >> 9;
            int r = (idx & 511) >> 3, c16 = idx & 7;
            const __half* src = qkv + (size_t)(b * SEQ + k0 + r) * 3 * EDIM +
                                (part ? 2 * EDIM : EDIM) + h * DDIM + c16 * 8;
            cpa16(base + part * 8192u + swz(r, c16), src);
        }
    };

    load_kv(0, ktlo);
    asm volatile("cp.async.commit_group;" ::: "memory");

    int brr = (lane & 7) + ((lane & 16) ? 8 : 0);
    int bc16 = (lane & 8) ? 1 : 0;
    int vrr = (lane & 7) + ((lane & 8) ? 8 : 0);
    int vc16 = (lane & 16) ? 1 : 0;

    for (int it = 0; it < nt; it++) {
        int kt = ktlo + it, k0 = kt * 64;
        if (it + 1 < nt) load_kv((it + 1) & 1, kt + 1);
        asm volatile("cp.async.commit_group;" ::: "memory");
        asm volatile("cp.async.wait_group 1;" ::: "memory");
        __syncthreads();

        bool active = (k0 <= qhi) && (k0 + 63 >= qlo - (MAXL - 1));
        if (active) {
            uint32_t kbase = sb + AT_ST + (uint32_t)(it & 1) * 16384u;
            uint32_t vbase = kbase + 8192u;

            float s[8][4];
#pragma unroll
            for (int nf = 0; nf < 8; nf++)
#pragma unroll
                for (int e = 0; e < 4; e++) s[nf][e] = 0.f;
#pragma unroll
            for (int kc = 0; kc < 4; kc++) {
                uint32_t kb[4][4];
#pragma unroll
                for (int t = 0; t < 4; t++)
                    ldm4(kb[t], kbase + swz(t * 16 + brr, kc * 2 + bc16));
#pragma unroll
                for (int nf = 0; nf < 8; nf++)
                    mma16816(s[nf], qf[kc], &kb[nf >> 1][(nf & 1) * 2]);
            }

            int qr0 = qlo + gid, qr1 = qr0 + 8;
            float tm0 = -1e30f, tm1 = -1e30f;
#pragma unroll
            for (int nf = 0; nf < 8; nf++) {
                int j0 = k0 + nf * 8 + tig * 2;
#pragma unroll
                for (int e = 0; e < 4; e++) {
                    int qi = (e & 2) ? qr1 : qr0;
                    int rel = qi - (j0 + (e & 1));
                    bool valid = (rel >= 0) && (rel < MAXL);
                    float v = valid ? s[nf][e] * 0.125f + srelp[valid ? rel : 0] : -1e30f;
                    s[nf][e] = v;
                    if (e & 2) tm1 = fmaxf(tm1, v); else tm0 = fmaxf(tm0, v);
                }
            }
            tm0 = fmaxf(tm0, __shfl_xor_sync(0xffffffffu, tm0, 1));
            tm0 = fmaxf(tm0, __shfl_xor_sync(0xffffffffu, tm0, 2));
            tm1 = fmaxf(tm1, __shfl_xor_sync(0xffffffffu, tm1, 1));
            tm1 = fmaxf(tm1, __shfl_xor_sync(0xffffffffu, tm1, 2));
            float n0 = fmaxf(m0, tm0), n1 = fmaxf(m1, tm1);
            float a0 = __expf(m0 - n0), a1 = __expf(m1 - n1);
            m0 = n0; m1 = n1;
            float ts0 = 0.f, ts1 = 0.f;
#pragma unroll
            for (int nf = 0; nf < 8; nf++) {
                s[nf][0] = __expf(s[nf][0] - n0);
                s[nf][1] = __expf(s[nf][1] - n0);
                s[nf][2] = __expf(s[nf][2] - n1);
                s[nf][3] = __expf(s[nf][3] - n1);
                ts0 += s[nf][0] + s[nf][1];
                ts1 += s[nf][2] + s[nf][3];
            }
            ts0 += __shfl_xor_sync(0xffffffffu, ts0, 1);
            ts0 += __shfl_xor_sync(0xffffffffu, ts0, 2);
            ts1 += __shfl_xor_sync(0xffffffffu, ts1, 1);
            ts1 += __shfl_xor_sync(0xffffffffu, ts1, 2);
            l0 = l0 * a0 + ts0;
            l1 = l1 * a1 + ts1;
#pragma unroll
            for (int nf = 0; nf < 8; nf++) {
                o[nf][0] *= a0; o[nf][1] *= a0;
                o[nf][2] *= a1; o[nf][3] *= a1;
            }

            uint32_t pf[4][4];
#pragma unroll
            for (int kc = 0; kc < 4; kc++) {
                pf[kc][0] = packh2(s[2 * kc][0], s[2 * kc][1]);
                pf[kc][1] = packh2(s[2 * kc][2], s[2 * kc][3]);
                pf[kc][2] = packh2(s[2 * kc + 1][0], s[2 * kc + 1][1]);
                pf[kc][3] = packh2(s[2 * kc + 1][2], s[2 * kc + 1][3]);
            }
#pragma unroll
            for (int kc = 0; kc < 4; kc++) {
                uint32_t vb[4][4];
#pragma unroll
                for (int vt = 0; vt < 4; vt++)
                    ldm4t(vb[vt], vbase + swz(kc * 16 + vrr, vt * 2 + vc16));
#pragma unroll
                for (int nf = 0; nf < 8; nf++)
                    mma16816(o[nf], pf[kc], &vb[nf >> 1][(nf & 1) * 2]);
            }
        }
        __syncthreads();
    }

    float i0 = 1.0f / l0, i1 = 1.0f / l1;
    int r0 = qlo + gid;
#pragma unroll
    for (int nf = 0; nf < 8; nf++) {
        int col = h * DDIM + nf * 8 + tig * 2;
        *(__half2*)(outp + (size_t)(b * SEQ + r0) * EDIM + col) =
            __floats2half2_rn(o[nf][0] * i0, o[nf][1] * i0);
        *(__half2*)(outp + (size_t)(b * SEQ + r0 + 8) * EDIM + col) =
            __floats2half2_rn(o[nf][2] * i1, o[nf][3] * i1);
    }
}

// ======================= launch =======================
extern "C" void kernel_launch(void* const* d_in, const int* in_sizes, int n_in,
                              void* d_out, int out_size) {
    (void)in_sizes; (void)n_in; (void)out_size;
    const float* x    = (const float*)d_in[0];
    const float* relp = (const float*)d_in[1];
    const float* ipw  = (const float*)d_in[2];
    const float* ipb  = (const float*)d_in[3];
    const float* ow   = (const float*)d_in[4];
    const float* ob   = (const float*)d_in[5];
    const float* w1   = (const float*)d_in[6];
    const float* b1   = (const float*)d_in[7];
    const float* w2   = (const float*)d_in[8];
    const float* b2   = (const float*)d_in[9];
    const float* g1   = (const float*)d_in[10];
    const float* be1  = (const float*)d_in[11];
    const float* g2   = (const float*)d_in[12];
    const float* be2  = (const float*)d_in[13];
    float* out = (float*)d_out;

    float* p_x1;
    __half *p_xn, *p_qkv, *p_att, *p_xm, *p_h;
    __half *p_ipw, *p_ow, *p_w1, *p_w2;
    cudaGetSymbolAddress((void**)&p_x1,  g_x1);
    cudaGetSymbolAddress((void**)&p_xn,  g_xn);
    cudaGetSymbolAddress((void**)&p_qkv, g_qkvh);
    cudaGetSymbolAddress((void**)&p_att, g_att);
    cudaGetSymbolAddress((void**)&p_xm,  g_xm);
    cudaGetSymbolAddress((void**)&p_h,   g_hb);
    cudaGetSymbolAddress((void**)&p_ipw, g_ipw16);
    cudaGetSymbolAddress((void**)&p_ow,  g_ow16);
    cudaGetSymbolAddress((void**)&p_w1,  g_w116);
    cudaGetSymbolAddress((void**)&p_w2,  g_w216);

    cudaFuncSetAttribute(gemm_mma<false, false, false>,
                         cudaFuncAttributeMaxDynamicSharedMemorySize, GSMEM);
    cudaFuncSetAttribute(gemm_mma<false, true, true>,
                         cudaFuncAttributeMaxDynamicSharedMemorySize, GSMEM);
    cudaFuncSetAttribute(gemm_mma<true, false, false>,
                         cudaFuncAttributeMaxDynamicSharedMemorySize, GSMEM);
    cudaFuncSetAttribute(attn_kernel,
                         cudaFuncAttributeMaxDynamicSharedMemorySize, AT_SMEM);

    // 0. fused weight convert (fp16)
    convert_all_kernel<<<(N4_TOT + 255) / 256, 256>>>(
        (const float4*)ipw, (const float4*)ow, (const float4*)w1, (const float4*)w2,
        (__half2*)p_ipw, (__half2*)p_ow, (__half2*)p_w1, (__half2*)p_w2);

    // 1. ln1 -> xn fp16
    ln_kernel<<<ROWS, 256>>>(x, g1, be1, p_xn);
    // 2. qkv (fp16 out)
    gemm_mma<false, false, false><<<dim3(24, 32), 256, GSMEM>>>(
        p_xn, p_ipw, ipb, nullptr, nullptr, p_qkv, 3 * EDIM, EDIM);
    // 3. flash attention (fp16 out)
    attn_kernel<<<dim3(SEQ / 128, BATCH * HNUM), 256, AT_SMEM>>>(p_qkv, relp, p_att);
    // 4. x1 = x + att @ ow^T + ob (fp32 out)
    gemm_mma<false, true, true><<<dim3(8, 32), 256, GSMEM>>>(
        p_att, p_ow, ob, x, p_x1, nullptr, EDIM, EDIM);
    // 5. ln2 -> xm fp16
    ln_kernel<<<ROWS, 256>>>(p_x1, g2, be2, p_xm);
    // 6. h = relu(xm @ w1^T + b1) fp16 out
    gemm_mma<true, false, false><<<dim3(32, 32), 256, GSMEM>>>(
        p_xm, p_w1, b1, nullptr, nullptr, p_h, 4 * EDIM, EDIM);
    // 7. out = x1 + h @ w2^T + b2 (fp32 out)
    gemm_mma<false, true, true><<<dim3(8, 32), 256, GSMEM>>>(
        p_h, p_w2, b2, p_x1, out, nullptr, EDIM, 4 * EDIM);
}

// round 15
// speedup vs baseline: 12.5358x; 1.0065x over previous
#include <cuda_runtime.h>
#include <cuda_fp16.h>
#include <math.h>
#include <stdint.h>

#define EDIM 1024
#define HNUM 16
#define DDIM 64
#define MAXL 512
#define BATCH 4
#define SEQ 1024
#define ROWS (BATCH * SEQ)   // 4096
#define EPSV 1e-5f

// ---------------- scratch ----------------
__device__ float g_x1[ROWS * EDIM];
__device__ __align__(16) __half g_xn  [ROWS * EDIM];
__device__ __align__(16) __half g_qkvh[ROWS * 3 * EDIM];
__device__ __align__(16) __half g_att [ROWS * EDIM];
__device__ __align__(16) __half g_xm  [ROWS * EDIM];
__device__ __align__(16) __half g_hb  [ROWS * 4 * EDIM];
__device__ __align__(16) __half g_ipw16[3 * EDIM * EDIM];
__device__ __align__(16) __half g_ow16 [EDIM * EDIM];
__device__ __align__(16) __half g_w116 [4 * EDIM * EDIM];
__device__ __align__(16) __half g_w216 [4 * EDIM * EDIM];

// ======================= helpers =======================
__device__ __forceinline__ uint32_t smem_u32(const void* p) {
    uint32_t a;
    asm("{ .reg .u64 t; cvta.to.shared.u64 t, %1; cvt.u32.u64 %0, t; }" : "=r"(a) : "l"(p));
    return a;
}
__device__ __forceinline__ void cpa16(uint32_t dst, const void* src) {
    asm volatile("cp.async.cg.shared.global [%0], [%1], 16;" :: "r"(dst), "l"(src));
}
__device__ __forceinline__ void ldm4(uint32_t* r, uint32_t addr) {
    asm volatile("ldmatrix.sync.aligned.m8n8.x4.shared.b16 {%0,%1,%2,%3}, [%4];"
                 : "=r"(r[0]), "=r"(r[1]), "=r"(r[2]), "=r"(r[3]) : "r"(addr));
}
__device__ __forceinline__ void ldm4t(uint32_t* r, uint32_t addr) {
    asm volatile("ldmatrix.sync.aligned.m8n8.x4.trans.shared.b16 {%0,%1,%2,%3}, [%4];"
                 : "=r"(r[0]), "=r"(r[1]), "=r"(r[2]), "=r"(r[3]) : "r"(addr));
}
__device__ __forceinline__ void mma16816(float* c, const uint32_t* a, const uint32_t* b) {
    asm volatile(
        "mma.sync.aligned.m16n8k16.row.col.f32.f16.f16.f32 "
        "{%0,%1,%2,%3}, {%4,%5,%6,%7}, {%8,%9}, {%0,%1,%2,%3};"
        : "+f"(c[0]), "+f"(c[1]), "+f"(c[2]), "+f"(c[3])
        : "r"(a[0]), "r"(a[1]), "r"(a[2]), "r"(a[3]), "r"(b[0]), "r"(b[1]));
}
__device__ __forceinline__ uint32_t packh2(float a, float b) {
    __half2 h = __floats2half2_rn(a, b);
    return *(uint32_t*)&h;
}
__device__ __forceinline__ uint32_t swz(int r, int c16) {
    return (uint32_t)(r * 128 + ((c16 ^ (r & 7)) << 4));
}

// ======================= fused weight convert fp32->fp16 =======================
#define N4_IPW (3 * EDIM * EDIM / 4)
#define N4_OW  (EDIM * EDIM / 4)
#define N4_W1  (4 * EDIM * EDIM / 4)
#define N4_W2  (4 * EDIM * EDIM / 4)
#define N4_TOT (N4_IPW + N4_OW + N4_W1 + N4_W2)

__global__ void convert_all_kernel(const float4* __restrict__ ipw,
                                   const float4* __restrict__ ow,
                                   const float4* __restrict__ w1,
                                   const float4* __restrict__ w2,
                                   __half2* __restrict__ ipwo, __half2* __restrict__ owo,
                                   __half2* __restrict__ w1o,  __half2* __restrict__ w2o) {
    int i = blockIdx.x * 256 + threadIdx.x;
    if (i >= N4_TOT) return;
    const float4* src;
    __half2* dst;
    int j = i;
    if (j < N4_IPW) { src = ipw; dst = ipwo; }
    else if ((j -= N4_IPW) < N4_OW) { src = ow; dst = owo; }
    else if ((j -= N4_OW) < N4_W1)  { src = w1; dst = w1o; }
    else { j -= N4_W1; src = w2; dst = w2o; }
    float4 f = src[j];
    dst[2 * j]     = __floats2half2_rn(f.x, f.y);
    dst[2 * j + 1] = __floats2half2_rn(f.z, f.w);
}

// ======================= LayerNorm (fp32 -> fp16) =======================
__global__ void ln_kernel(const float* __restrict__ x,
                          const float* __restrict__ g,
                          const float* __restrict__ b,
                          __half* __restrict__ o) {
    int row = blockIdx.x;
    int tid = threadIdx.x;
    const float4* xr = (const float4*)(x + (size_t)row * EDIM);
    float4 v = xr[tid];
    float s  = v.x + v.y + v.z + v.w;
    float ss = v.x * v.x + v.y * v.y + v.z * v.z + v.w * v.w;
#pragma unroll
    for (int of = 16; of > 0; of >>= 1) {
        s  += __shfl_xor_sync(0xffffffffu, s,  of);
        ss += __shfl_xor_sync(0xffffffffu, ss, of);
    }
    __shared__ float rs[8], rss[8];
    __shared__ float s_mu, s_rstd;
    if ((tid & 31) == 0) { rs[tid >> 5] = s; rss[tid >> 5] = ss; }
    __syncthreads();
    if (tid == 0) {
        float S = 0.f, SS = 0.f;
#pragma unroll
        for (int i = 0; i < 8; i++) { S += rs[i]; SS += rss[i]; }
        float mu = S * (1.0f / EDIM);
        float var = SS * (1.0f / EDIM) - mu * mu;
        s_mu = mu; s_rstd = rsqrtf(var + EPSV);
    }
    __syncthreads();
    float mu = s_mu, rstd = s_rstd;
    float4 gg = ((const float4*)g)[tid];
    float4 bb = ((const float4*)b)[tid];
    __half2* po = (__half2*)(o + (size_t)row * EDIM);
    po[2 * tid]     = __floats2half2_rn((v.x - mu) * rstd * gg.x + bb.x,
                                        (v.y - mu) * rstd * gg.y + bb.y);
    po[2 * tid + 1] = __floats2half2_rn((v.z - mu) * rstd * gg.z + bb.z,
                                        (v.w - mu) * rstd * gg.w + bb.w);
}

// ======================= fp16 GEMM, 3-stage pipeline =======================
#define TIL 16384u
#define STG (2u * TIL)
#define GSMEM (3u * STG)           // 98304

template <bool RELU, bool RES, bool OUTF32>
__global__ void __launch_bounds__(256, 2)
gemm_mma(const __half* __restrict__ A, const __half* __restrict__ B,
         const float* __restrict__ bias, const float* __restrict__ res,
         float* __restrict__ C, __half* __restrict__ Ch, int Nc, int K) {
    extern __shared__ char sm[];
    uint32_t sb = smem_u32(sm);
    int tid = threadIdx.x;
    int wid = tid >> 5, lane = tid & 31;
    int wm = wid & 1, wn = wid >> 1;
    int brow = blockIdx.y * 128, bcol = blockIdx.x * 128;

    float acc[4][4][4];
#pragma unroll
    for (int i = 0; i < 4; i++)
#pragma unroll
        for (int j = 0; j < 4; j++)
#pragma unroll
            for (int k = 0; k < 4; k++) acc[i][j][k] = 0.f;

    int nchunk = K >> 6;
    auto load_stage = [&](int st, int k0) {
        uint32_t base = sb + (uint32_t)st * STG;
#pragma unroll
        for (int i = 0; i < 8; i++) {
            int idx = tid + i * 256;
            int part = idx >> 10;
            int r = (idx & 1023) >> 3, c16 = idx & 7;
            uint32_t d = base + part * TIL + swz(r, c16);
            const __half* src = (part == 0)
                ? A + (size_t)(brow + r) * K + k0 + c16 * 8
                : B + (size_t)(bcol + r) * K + k0 + c16 * 8;
            cpa16(d, src);
        }
    };

    load_stage(0, 0);
    asm volatile("cp.async.commit_group;" ::: "memory");
    if (nchunk > 1) load_stage(1, 64);
    asm volatile("cp.async.commit_group;" ::: "memory");

    int l15 = lane & 15;
    int ac16 = (lane & 16) ? 1 : 0;
    int brr = (lane & 7) + ((lane & 16) ? 8 : 0);
    int bc16 = (lane & 8) ? 1 : 0;

    int stage = 0;
    for (int ch = 0; ch < nchunk; ch++) {
        asm volatile("cp.async.wait_group 1;" ::: "memory");
        __syncthreads();
        if (ch + 2 < nchunk) {
            int ns = stage + 2; if (ns >= 3) ns -= 3;
            load_stage(ns, (ch + 2) * 64);
        }
        asm volatile("cp.async.commit_group;" ::: "memory");

        uint32_t base = sb + (uint32_t)stage * STG;
#pragma unroll
        for (int kc = 0; kc < 4; kc++) {
            uint32_t kb[2][4];
#pragma unroll
            for (int p = 0; p < 2; p++)
                ldm4(kb[p], base + TIL + swz(wn * 32 + p * 16 + brr, kc * 2 + bc16));
#pragma unroll
            for (int mf = 0; mf < 4; mf++) {
                uint32_t a[4];
                ldm4(a, base + swz(wm * 64 + mf * 16 + l15, kc * 2 + ac16));
#pragma unroll
                for (int nf = 0; nf < 4; nf++)
                    mma16816(acc[mf][nf], a, &kb[nf >> 1][(nf & 1) * 2]);
            }
        }
        if (++stage >= 3) stage = 0;
    }
    __syncthreads();

    int gid = lane >> 2, tig = lane & 3;
#pragma unroll
    for (int mf = 0; mf < 4; mf++) {
#pragma unroll
        for (int nf = 0; nf < 4; nf++) {
            int col = bcol + wn * 32 + nf * 8 + tig * 2;
            float b0 = bias[col], b1 = bias[col + 1];
#pragma unroll
            for (int hr = 0; hr < 2; hr++) {
                int row = brow + wm * 64 + mf * 16 + gid + hr * 8;
                float v0 = acc[mf][nf][hr * 2 + 0] + b0;
                float v1 = acc[mf][nf][hr * 2 + 1] + b1;
                if (RELU) { v0 = fmaxf(v0, 0.f); v1 = fmaxf(v1, 0.f); }
                if (RES) {
                    float2 r2 = *(const float2*)(res + (size_t)row * Nc + col);
                    v0 += r2.x; v1 += r2.y;
                }
                if (OUTF32) {
                    float2 o2; o2.x = v0; o2.y = v1;
                    *(float2*)(C + (size_t)row * Nc + col) = o2;
                } else {
                    *(__half2*)(Ch + (size_t)row * Nc + col) = __floats2half2_rn(v0, v1);
                }
            }
        }
    }
}

// ======================= flash attention (mma.sync fp16) =======================
// Block: 128 queries x (b,h); 8 warps of 16 queries. Key tiles of 64, dbl-buffered.
// 2 CTAs/SM (reg cap 128); heavy q-tiles scheduled first.
#define AT_SQ   0u
#define AT_RP   16384u
#define AT_ST   18432u
#define AT_SMEM (18432u + 2u * 16384u)

__global__ void __launch_bounds__(256, 2)
attn_kernel(const __half* __restrict__ qkv, const float* __restrict__ relp,
            __half* __restrict__ outp) {
    extern __shared__ char sm[];
    uint32_t sb = smem_u32(sm);
    float* srelp = (float*)(sm + AT_RP);
    int tid = threadIdx.x;
    int w = tid >> 5, lane = tid & 31;
    int gid = lane >> 2, tig = lane & 3;
    int qt = gridDim.x - 1 - blockIdx.x;      // heavy tiles first
    int q0 = qt * 128;
    int bh = blockIdx.y;
    int b = bh >> 4, h = bh & 15;

#pragma unroll
    for (int i = 0; i < 2; i++) srelp[tid + i * 256] = relp[h * MAXL + tid + i * 256];
#pragma unroll
    for (int i = 0; i < 4; i++) {
        int idx = tid + i * 256;
        int r = idx >> 3, c16 = idx & 7;
        uint4 q4 = *(const uint4*)(qkv + (size_t)(b * SEQ + q0 + r) * 3 * EDIM +
                                   h * DDIM + c16 * 8);
        *(uint4*)(sm + AT_SQ + swz(r, c16)) = q4;
    }
    __syncthreads();

    uint32_t qf[4][4];
    int l15 = lane & 15;
    int ac16 = (lane & 16) ? 1 : 0;
#pragma unroll
    for (int kc = 0; kc < 4; kc++)
        ldm4(qf[kc], sb + AT_SQ + swz(w * 16 + l15, kc * 2 + ac16));

    float o[8][4];
#pragma unroll
    for (int nf = 0; nf < 8; nf++)
#pragma unroll
        for (int e = 0; e < 4; e++) o[nf][e] = 0.f;
    float m0 = -1e30f, m1 = -1e30f, l0 = 0.f, l1 = 0.f;

    int ktlo = 2 * qt - 8; if (ktlo < 0) ktlo = 0;
    int kthi = 2 * qt + 1;
    int nt = kthi - ktlo + 1;
    int qlo = q0 + w * 16, qhi = qlo + 15;

    auto load_kv = [&](int st, int kt) {
        uint32_t base = sb + AT_ST + (uint32_t)st * 16384u;
        int k0 = kt * 64;
#pragma unroll
        for (int i = 0; i < 4; i++) {
            int idx = tid + i * 256;
            int part = idx >> 9;
            int r = (idx & 511) >> 3, c16 = idx & 7;
            const __half* src = qkv + (size_t)(b * SEQ + k0 + r) * 3 * EDIM +
                                (part ? 2 * EDIM : EDIM) + h * DDIM + c16 * 8;
            cpa16(base + part * 8192u + swz(r, c16), src);
        }
    };

    load_kv(0, ktlo);
    asm volatile("cp.async.commit_group;" ::: "memory");

    int brr = (lane & 7) + ((lane & 16) ? 8 : 0);
    int bc16 = (lane & 8) ? 1 : 0;
    int vrr = (lane & 7) + ((lane & 8) ? 8 : 0);
    int vc16 = (lane & 16) ? 1 : 0;

    for (int it = 0; it < nt; it++) {
        int kt = ktlo + it, k0 = kt * 64;
        if (it + 1 < nt) load_kv((it + 1) & 1, kt + 1);
        asm volatile("cp.async.commit_group;" ::: "memory");
        asm volatile("cp.async.wait_group 1;" ::: "memory");
        __syncthreads();

        bool active = (k0 <= qhi) && (k0 + 63 >= qlo - (MAXL - 1));
        if (active) {
            uint32_t kbase = sb + AT_ST + (uint32_t)(it & 1) * 16384u;
            uint32_t vbase = kbase + 8192u;

            float s[8][4];
#pragma unroll
            for (int nf = 0; nf < 8; nf++)
#pragma unroll
                for (int e = 0; e < 4; e++) s[nf][e] = 0.f;
#pragma unroll
            for (int kc = 0; kc < 4; kc++) {
                uint32_t kb[4][4];
#pragma unroll
                for (int t = 0; t < 4; t++)
                    ldm4(kb[t], kbase + swz(t * 16 + brr, kc * 2 + bc16));
#pragma unroll
                for (int nf = 0; nf < 8; nf++)
                    mma16816(s[nf], qf[kc], &kb[nf >> 1][(nf & 1) * 2]);
            }

            int qr0 = qlo + gid, qr1 = qr0 + 8;
            float tm0 = -1e30f, tm1 = -1e30f;
#pragma unroll
            for (int nf = 0; nf < 8; nf++) {
                int j0 = k0 + nf * 8 + tig * 2;
#pragma unroll
                for (int e = 0; e < 4; e++) {
                    int qi = (e & 2) ? qr1 : qr0;
                    int rel = qi - (j0 + (e & 1));
                    bool valid = (rel >= 0) && (rel < MAXL);
                    float v = valid ? s[nf][e] * 0.125f + srelp[valid ? rel : 0] : -1e30f;
                    s[nf][e] = v;
                    if (e & 2) tm1 = fmaxf(tm1, v); else tm0 = fmaxf(tm0, v);
                }
            }
            tm0 = fmaxf(tm0, __shfl_xor_sync(0xffffffffu, tm0, 1));
            tm0 = fmaxf(tm0, __shfl_xor_sync(0xffffffffu, tm0, 2));
            tm1 = fmaxf(tm1, __shfl_xor_sync(0xffffffffu, tm1, 1));
            tm1 = fmaxf(tm1, __shfl_xor_sync(0xffffffffu, tm1, 2));
            float n0 = fmaxf(m0, tm0), n1 = fmaxf(m1, tm1);
            float a0 = __expf(m0 - n0), a1 = __expf(m1 - n1);
            m0 = n0; m1 = n1;
            float ts0 = 0.f, ts1 = 0.f;
#pragma unroll
            for (int nf = 0; nf < 8; nf++) {
                s[nf][0] = __expf(s[nf][0] - n0);
                s[nf][1] = __expf(s[nf][1] - n0);
                s[nf][2] = __expf(s[nf][2] - n1);
                s[nf][3] = __expf(s[nf][3] - n1);
                ts0 += s[nf][0] + s[nf][1];
                ts1 += s[nf][2] + s[nf][3];
            }
            ts0 += __shfl_xor_sync(0xffffffffu, ts0, 1);
            ts0 += __shfl_xor_sync(0xffffffffu, ts0, 2);
            ts1 += __shfl_xor_sync(0xffffffffu, ts1, 1);
            ts1 += __shfl_xor_sync(0xffffffffu, ts1, 2);
            l0 = l0 * a0 + ts0;
            l1 = l1 * a1 + ts1;
#pragma unroll
            for (int nf = 0; nf < 8; nf++) {
                o[nf][0] *= a0; o[nf][1] *= a0;
                o[nf][2] *= a1; o[nf][3] *= a1;
            }

            uint32_t pf[4][4];
#pragma unroll
            for (int kc = 0; kc < 4; kc++) {
                pf[kc][0] = packh2(s[2 * kc][0], s[2 * kc][1]);
                pf[kc][1] = packh2(s[2 * kc][2], s[2 * kc][3]);
                pf[kc][2] = packh2(s[2 * kc + 1][0], s[2 * kc + 1][1]);
                pf[kc][3] = packh2(s[2 * kc + 1][2], s[2 * kc + 1][3]);
            }
#pragma unroll
            for (int kc = 0; kc < 4; kc++) {
                uint32_t vb[4][4];
#pragma unroll
                for (int vt = 0; vt < 4; vt++)
                    ldm4t(vb[vt], vbase + swz(kc * 16 + vrr, vt * 2 + vc16));
#pragma unroll
                for (int nf = 0; nf < 8; nf++)
                    mma16816(o[nf], pf[kc], &vb[nf >> 1][(nf & 1) * 2]);
            }
        }
        __syncthreads();
    }

    float i0 = 1.0f / l0, i1 = 1.0f / l1;
    int r0 = qlo + gid;
#pragma unroll
    for (int nf = 0; nf < 8; nf++) {
        int col = h * DDIM + nf * 8 + tig * 2;
        *(__half2*)(outp + (size_t)(b * SEQ + r0) * EDIM + col) =
            __floats2half2_rn(o[nf][0] * i0, o[nf][1] * i0);
        *(__half2*)(outp + (size_t)(b * SEQ + r0 + 8) * EDIM + col) =
            __floats2half2_rn(o[nf][2] * i1, o[nf][3] * i1);
    }
}

// ======================= launch =======================
extern "C" void kernel_launch(void* const* d_in, const int* in_sizes, int n_in,
                              void* d_out, int out_size) {
    (void)in_sizes; (void)n_in; (void)out_size;
    const float* x    = (const float*)d_in[0];
    const float* relp = (const float*)d_in[1];
    const float* ipw  = (const float*)d_in[2];
    const float* ipb  = (const float*)d_in[3];
    const float* ow   = (const float*)d_in[4];
    const float* ob   = (const float*)d_in[5];
    const float* w1   = (const float*)d_in[6];
    const float* b1   = (const float*)d_in[7];
    const float* w2   = (const float*)d_in[8];
    const float* b2   = (const float*)d_in[9];
    const float* g1   = (const float*)d_in[10];
    const float* be1  = (const float*)d_in[11];
    const float* g2   = (const float*)d_in[12];
    const float* be2  = (const float*)d_in[13];
    float* out = (float*)d_out;

    float* p_x1;
    __half *p_xn, *p_qkv, *p_att, *p_xm, *p_h;
    __half *p_ipw, *p_ow, *p_w1, *p_w2;
    cudaGetSymbolAddress((void**)&p_x1,  g_x1);
    cudaGetSymbolAddress((void**)&p_xn,  g_xn);
    cudaGetSymbolAddress((void**)&p_qkv, g_qkvh);
    cudaGetSymbolAddress((void**)&p_att, g_att);
    cudaGetSymbolAddress((void**)&p_xm,  g_xm);
    cudaGetSymbolAddress((void**)&p_h,   g_hb);
    cudaGetSymbolAddress((void**)&p_ipw, g_ipw16);
    cudaGetSymbolAddress((void**)&p_ow,  g_ow16);
    cudaGetSymbolAddress((void**)&p_w1,  g_w116);
    cudaGetSymbolAddress((void**)&p_w2,  g_w216);

    cudaFuncSetAttribute(gemm_mma<false, false, false>,
                         cudaFuncAttributeMaxDynamicSharedMemorySize, GSMEM);
    cudaFuncSetAttribute(gemm_mma<false, true, true>,
                         cudaFuncAttributeMaxDynamicSharedMemorySize, GSMEM);
    cudaFuncSetAttribute(gemm_mma<true, false, false>,
                         cudaFuncAttributeMaxDynamicSharedMemorySize, GSMEM);
    cudaFuncSetAttribute(attn_kernel,
                         cudaFuncAttributeMaxDynamicSharedMemorySize, AT_SMEM);

    // 0. fused weight convert (fp16)
    convert_all_kernel<<<(N4_TOT + 255) / 256, 256>>>(
        (const float4*)ipw, (const float4*)ow, (const float4*)w1, (const float4*)w2,
        (__half2*)p_ipw, (__half2*)p_ow, (__half2*)p_w1, (__half2*)p_w2);

    // 1. ln1 -> xn fp16
    ln_kernel<<<ROWS, 256>>>(x, g1, be1, p_xn);
    // 2. qkv (fp16 out)
    gemm_mma<false, false, false><<<dim3(24, 32), 256, GSMEM>>>(
        p_xn, p_ipw, ipb, nullptr, nullptr, p_qkv, 3 * EDIM, EDIM);
    // 3. flash attention (fp16 out)
    attn_kernel<<<dim3(SEQ / 128, BATCH * HNUM), 256, AT_SMEM>>>(p_qkv, relp, p_att);
    // 4. x1 = x + att @ ow^T + ob (fp32 out)
    gemm_mma<false, true, true><<<dim3(8, 32), 256, GSMEM>>>(
        p_att, p_ow, ob, x, p_x1, nullptr, EDIM, EDIM);
    // 5. ln2 -> xm fp16
    ln_kernel<<<ROWS, 256>>>(p_x1, g2, be2, p_xm);
    // 6. h = relu(xm @ w1^T + b1) fp16 out
    gemm_mma<true, false, false><<<dim3(32, 32), 256, GSMEM>>>(
        p_xm, p_w1, b1, nullptr, nullptr, p_h, 4 * EDIM, EDIM);
    // 7. out = x1 + h @ w2^T + b2 (fp32 out)
    gemm_mma<false, true, true><<<dim3(8, 32), 256, GSMEM>>>(
        p_h, p_w2, b2, p_x1, out, nullptr, EDIM, 4 * EDIM);
}